// round 9
// baseline (speedup 1.0000x reference)
#include <cuda_runtime.h>
#include <cstdint>

// CTNNBackflowStyleJastrow: B=1024, N=32, D=3, H=M=32, RH=64
// One CTA (256 threads = 8 warps) per batch element.
// Edge loop: per warp, 2 rows i at a time -> M=64 tf32 mma.sync GEMMs with
// register-resident weight B-fragments. Row/pair reductions done IN REGISTERS
// on the mma C-fragments (masked adds + shfl butterfly) -- no stage-4 stores,
// no smem readback loop.

__device__ __forceinline__ float silu_f(float x) {
    return __fdividef(x, 1.0f + __expf(-x));
}
__device__ __forceinline__ uint32_t f2tf(float f) {
    uint32_t r; asm("cvt.rna.tf32.f32 %0, %1;" : "=r"(r) : "f"(f)); return r;
}
__device__ __forceinline__ float tfbits(float f) {
    return __uint_as_float(f2tf(f));
}
__device__ __forceinline__ void mma_tf32(float& d0, float& d1, float& d2, float& d3,
                                         uint32_t a0, uint32_t a1, uint32_t a2, uint32_t a3,
                                         uint32_t b0, uint32_t b1) {
    asm volatile("mma.sync.aligned.m16n8k8.row.col.f32.tf32.tf32.f32 "
                 "{%0,%1,%2,%3}, {%4,%5,%6,%7}, {%8,%9}, {%0,%1,%2,%3};"
                 : "+f"(d0), "+f"(d1), "+f"(d2), "+f"(d3)
                 : "r"(a0), "r"(a1), "r"(a2), "r"(a3), "r"(b0), "r"(b1));
}

#define ST 36   // buffer stride: A-frag loads conflict-free (4*gid+tig distinct banks)

__global__ __launch_bounds__(256, 1)
void jastrow_kernel(const float* __restrict__ x,
                    const float* __restrict__ W_node, const float* __restrict__ b_node,
                    const float* __restrict__ We1,  const float* __restrict__ be1,
                    const float* __restrict__ We2,  const float* __restrict__ be2,
                    const float* __restrict__ Wv2e, const float* __restrict__ We2v,
                    const float* __restrict__ Wu1,  const float* __restrict__ bu1,
                    const float* __restrict__ Wu2,  const float* __restrict__ bu2,
                    const float* __restrict__ Wn1,  const float* __restrict__ bn1,
                    const float* __restrict__ Wn2,  const float* __restrict__ bn2,
                    const float* __restrict__ Wf1,  const float* __restrict__ bf1,
                    const float* __restrict__ Wf2,  const float* __restrict__ bf2,
                    const float* __restrict__ Wf3,  const float* __restrict__ bf3,
                    float* __restrict__ out)
{
    __shared__ float sx[96];
    __shared__ float shv[32 * 33];
    __shared__ float sp [32 * 33];
    __shared__ __align__(8) float sq [32 * 34];
    __shared__ __align__(8) float ssj[32 * 34];
    __shared__ float srs[32 * 33];
    __shared__ __align__(8) float sbe1[32], sbe2[32], sbu2[32];
    __shared__ float spair[32];
    __shared__ float sred[3];
    __shared__ float sfin[132], sf1[64], sf2[64];
    extern __shared__ __align__(16) float dynsmem[];   // per warp: Tb[64*ST] + HE[64*ST]

    const int tid  = threadIdx.x;
    const int lane = tid & 31;
    const int w    = tid >> 5;
    const int b    = blockIdx.x;
    const int gid  = lane >> 2;
    const int tig  = lane & 3;

    // ---- register-resident tf32 weight B-fragments ----
    uint32_t bWe1[8], bWe2[32], bWu1[32], bWu2[32];
    #pragma unroll
    for (int nt = 0; nt < 4; nt++) {
        int n = 8 * nt + gid;
        bWe1[nt * 2 + 0] = f2tf(We1[n * 5 + tig]);
        bWe1[nt * 2 + 1] = (tig == 0) ? f2tf(We1[n * 5 + 4]) : 0u;
        #pragma unroll
        for (int kt = 0; kt < 4; kt++) {
            int k = 8 * kt + tig;
            bWe2[nt * 8 + kt * 2 + 0] = f2tf(We2[n * 32 + k]);
            bWe2[nt * 8 + kt * 2 + 1] = f2tf(We2[n * 32 + k + 4]);
            bWu1[nt * 8 + kt * 2 + 0] = f2tf(Wu1[n * 96 + k]);
            bWu1[nt * 8 + kt * 2 + 1] = f2tf(Wu1[n * 96 + k + 4]);
            bWu2[nt * 8 + kt * 2 + 0] = f2tf(Wu2[n * 32 + k]);
            bWu2[nt * 8 + kt * 2 + 1] = f2tf(Wu2[n * 32 + k + 4]);
        }
    }

    if (tid < 96) sx[tid] = x[b * 96 + tid];
    if (tid < 32) {
        spair[tid] = 0.0f;
        sbe1[tid] = be1[tid]; sbe2[tid] = be2[tid]; sbu2[tid] = bu2[tid];
    }
    if (tid < 3)  sred[tid] = 0.0f;
    __syncthreads();

    // ---- node phases ----
    #pragma unroll
    for (int it = 0; it < 4; it++) {
        int ch = w + it * 8;
        int i  = lane;
        float sf = (i >= 16) ? 1.0f : 0.0f;
        float a = b_node[ch]
                + W_node[ch * 4 + 0] * sx[i * 3 + 0]
                + W_node[ch * 4 + 1] * sx[i * 3 + 1]
                + W_node[ch * 4 + 2] * sx[i * 3 + 2]
                + W_node[ch * 4 + 3] * sf;
        shv[i * 33 + ch] = a;
    }
    __syncthreads();

    #pragma unroll
    for (int it = 0; it < 4; it++) {
        int m = w + it * 8;
        int i = lane;
        float a0 = 0.f, a1 = 0.f;
        #pragma unroll
        for (int h = 0; h < 32; h += 2) {
            a0 = fmaf(Wv2e[m * 32 + h + 0], shv[i * 33 + h + 0], a0);
            a1 = fmaf(Wv2e[m * 32 + h + 1], shv[i * 33 + h + 1], a1);
        }
        sp[i * 33 + m] = a0 + a1;
    }
    __syncthreads();

    #pragma unroll
    for (int it = 0; it < 4; it++) {
        int h = w + it * 8;
        int i = lane;
        float aq = bu1[h], as = 0.f;
        #pragma unroll
        for (int m = 0; m < 32; m++) {
            float pv = sp[i * 33 + m];
            aq = fmaf(Wu1[h * 96 + 32 + m], pv, aq);
            as = fmaf(Wu1[h * 96 + 64 + m], pv, as);
        }
        sq [i * 34 + h] = aq;
        ssj[i * 34 + h] = as;
    }
    __syncthreads();

    // ---- edge loop: warp w owns rows 4w..4w+3, processed 2 at a time (M=64) ----
    float* Tb = dynsmem + w * (2 * 64 * ST);
    float* HE = Tb + 64 * ST;
    float* F  = HE;                       // stage-1 features alias HE (stride 12)

    const float xj0 = sx[lane * 3 + 0], xj1 = sx[lane * 3 + 1], xj2 = sx[lane * 3 + 2];
    float psum[8];
    #pragma unroll
    for (int v = 0; v < 8; v++) psum[v] = 0.0f;

    #pragma unroll 1
    for (int it = 0; it < 2; it++) {
        const int i0 = w * 4 + 2 * it;
        const int i1 = i0 + 1;

        // features: lane writes rows (ip=0, j=lane) and (ip=1, j=lane)
        __syncwarp();   // prior it's stage-3 HE reads done (F aliases HE)
        {
            float fr0 = sx[i0 * 3 + 0] - xj0;
            float fr1 = sx[i0 * 3 + 1] - xj1;
            float fr2 = sx[i0 * 3 + 2] - xj2;
            float rr2 = fmaf(fr0, fr0, fmaf(fr1, fr1, fr2 * fr2));
            float tpl = rr2 + 1e-12f;
            float rr1 = tpl * __frsqrt_rn(tpl);
            *reinterpret_cast<float4*>(&F[lane * 12]) =
                make_float4(tfbits(fr0), tfbits(fr1), tfbits(fr2), tfbits(rr1));
            *reinterpret_cast<float4*>(&F[lane * 12 + 4]) =
                make_float4(tfbits(rr2), 0.0f, 0.0f, 0.0f);

            float gr0 = sx[i1 * 3 + 0] - xj0;
            float gr1 = sx[i1 * 3 + 1] - xj1;
            float gr2 = sx[i1 * 3 + 2] - xj2;
            float gg2 = fmaf(gr0, gr0, fmaf(gr1, gr1, gr2 * gr2));
            float gpl = gg2 + 1e-12f;
            float gg1 = gpl * __frsqrt_rn(gpl);
            *reinterpret_cast<float4*>(&F[(lane + 32) * 12]) =
                make_float4(tfbits(gr0), tfbits(gr1), tfbits(gr2), tfbits(gg1));
            *reinterpret_cast<float4*>(&F[(lane + 32) * 12 + 4]) =
                make_float4(tfbits(gg2), 0.0f, 0.0f, 0.0f);
        }
        __syncwarp();

        // stage 1: Tb = silu(F @ We1^T + be1)
        #pragma unroll
        for (int mt = 0; mt < 4; mt++) {
            uint32_t A0 = __float_as_uint(F[(16 * mt + gid) * 12 + tig]);
            uint32_t A1 = __float_as_uint(F[(16 * mt + gid + 8) * 12 + tig]);
            uint32_t A2 = __float_as_uint(F[(16 * mt + gid) * 12 + tig + 4]);
            uint32_t A3 = __float_as_uint(F[(16 * mt + gid + 8) * 12 + tig + 4]);
            #pragma unroll
            for (int nt = 0; nt < 4; nt++) {
                int col = 8 * nt + 2 * tig;
                float2 bb = *reinterpret_cast<const float2*>(&sbe1[col]);
                float d0 = bb.x, d1 = bb.y, d2 = bb.x, d3 = bb.y;
                mma_tf32(d0, d1, d2, d3, A0, A1, A2, A3, bWe1[nt * 2], bWe1[nt * 2 + 1]);
                int r0 = (16 * mt + gid) * ST + col;
                *reinterpret_cast<float2*>(&Tb[r0]) =
                    make_float2(tfbits(silu_f(d0)), tfbits(silu_f(d1)));
                *reinterpret_cast<float2*>(&Tb[r0 + 8 * ST]) =
                    make_float2(tfbits(silu_f(d2)), tfbits(silu_f(d3)));
            }
        }
        __syncwarp();

        // stage 2: HE = Tb @ We2^T + be2 ; masked he -> psum (in regs)
        #pragma unroll
        for (int mt = 0; mt < 4; mt++) {
            uint32_t Ar[16];
            #pragma unroll
            for (int kt = 0; kt < 4; kt++) {
                const float* p0 = &Tb[(16 * mt + gid) * ST + 8 * kt + tig];
                const float* p1 = &Tb[(16 * mt + gid + 8) * ST + 8 * kt + tig];
                Ar[4 * kt + 0] = __float_as_uint(p0[0]);
                Ar[4 * kt + 1] = __float_as_uint(p1[0]);
                Ar[4 * kt + 2] = __float_as_uint(p0[4]);
                Ar[4 * kt + 3] = __float_as_uint(p1[4]);
            }
            const int icur = i0 + (mt >> 1);
            const int jlo  = ((mt & 1) << 4) + gid;
            const int jhi  = jlo + 8;
            const bool plo = (jlo > icur), phi = (jhi > icur);
            #pragma unroll
            for (int nt = 0; nt < 4; nt++) {
                int col = 8 * nt + 2 * tig;
                float2 bb = *reinterpret_cast<const float2*>(&sbe2[col]);
                float d0 = bb.x, d1 = bb.y, d2 = bb.x, d3 = bb.y;
                #pragma unroll
                for (int kt = 0; kt < 4; kt++)
                    mma_tf32(d0, d1, d2, d3,
                             Ar[4 * kt + 0], Ar[4 * kt + 1], Ar[4 * kt + 2], Ar[4 * kt + 3],
                             bWe2[nt * 8 + kt * 2], bWe2[nt * 8 + kt * 2 + 1]);
                int r0 = (16 * mt + gid) * ST + col;
                *reinterpret_cast<float2*>(&HE[r0]) = make_float2(tfbits(d0), tfbits(d1));
                *reinterpret_cast<float2*>(&HE[r0 + 8 * ST]) = make_float2(tfbits(d2), tfbits(d3));
                if (plo) { psum[nt * 2] += d0; psum[nt * 2 + 1] += d1; }
                if (phi) { psum[nt * 2] += d2; psum[nt * 2 + 1] += d3; }
            }
        }
        __syncwarp();

        // stage 3: Tb = silu(HE @ Wu1a^T + q_i + s_j)
        #pragma unroll
        for (int mt = 0; mt < 4; mt++) {
            uint32_t Ar[16];
            #pragma unroll
            for (int kt = 0; kt < 4; kt++) {
                const float* p0 = &HE[(16 * mt + gid) * ST + 8 * kt + tig];
                const float* p1 = &HE[(16 * mt + gid + 8) * ST + 8 * kt + tig];
                Ar[4 * kt + 0] = __float_as_uint(p0[0]);
                Ar[4 * kt + 1] = __float_as_uint(p1[0]);
                Ar[4 * kt + 2] = __float_as_uint(p0[4]);
                Ar[4 * kt + 3] = __float_as_uint(p1[4]);
            }
            const int icur = i0 + (mt >> 1);
            const int jlo  = ((mt & 1) << 4) + gid;
            #pragma unroll
            for (int nt = 0; nt < 4; nt++) {
                int col = 8 * nt + 2 * tig;
                float2 qv = *reinterpret_cast<const float2*>(&sq[icur * 34 + col]);
                float2 s0 = *reinterpret_cast<const float2*>(&ssj[jlo * 34 + col]);
                float2 s1 = *reinterpret_cast<const float2*>(&ssj[(jlo + 8) * 34 + col]);
                float d0 = qv.x + s0.x, d1 = qv.y + s0.y;
                float d2 = qv.x + s1.x, d3 = qv.y + s1.y;
                #pragma unroll
                for (int kt = 0; kt < 4; kt++)
                    mma_tf32(d0, d1, d2, d3,
                             Ar[4 * kt + 0], Ar[4 * kt + 1], Ar[4 * kt + 2], Ar[4 * kt + 3],
                             bWu1[nt * 8 + kt * 2], bWu1[nt * 8 + kt * 2 + 1]);
                int r0 = (16 * mt + gid) * ST + col;
                *reinterpret_cast<float2*>(&Tb[r0]) =
                    make_float2(tfbits(silu_f(d0)), tfbits(silu_f(d1)));
                *reinterpret_cast<float2*>(&Tb[r0 + 8 * ST]) =
                    make_float2(tfbits(silu_f(d2)), tfbits(silu_f(d3)));
            }
        }
        __syncwarp();

        // stage 4: hn = Tb @ Wu2^T + bu2 -- NO stores; masked adds into rs/psum
        float rs0[8], rs1[8];
        #pragma unroll
        for (int v = 0; v < 8; v++) { rs0[v] = 0.0f; rs1[v] = 0.0f; }
        #pragma unroll
        for (int mt = 0; mt < 4; mt++) {
            uint32_t Ar[16];
            #pragma unroll
            for (int kt = 0; kt < 4; kt++) {
                const float* p0 = &Tb[(16 * mt + gid) * ST + 8 * kt + tig];
                const float* p1 = &Tb[(16 * mt + gid + 8) * ST + 8 * kt + tig];
                Ar[4 * kt + 0] = __float_as_uint(p0[0]);
                Ar[4 * kt + 1] = __float_as_uint(p1[0]);
                Ar[4 * kt + 2] = __float_as_uint(p0[4]);
                Ar[4 * kt + 3] = __float_as_uint(p1[4]);
            }
            const int icur = i0 + (mt >> 1);
            const int jlo  = ((mt & 1) << 4) + gid;
            const int jhi  = jlo + 8;
            const bool plo = (jlo > icur),  phi = (jhi > icur);
            const bool nlo = (jlo != icur), nhi = (jhi != icur);
            #pragma unroll
            for (int nt = 0; nt < 4; nt++) {
                int col = 8 * nt + 2 * tig;
                float2 bb = *reinterpret_cast<const float2*>(&sbu2[col]);
                float d0 = bb.x, d1 = bb.y, d2 = bb.x, d3 = bb.y;
                #pragma unroll
                for (int kt = 0; kt < 4; kt++)
                    mma_tf32(d0, d1, d2, d3,
                             Ar[4 * kt + 0], Ar[4 * kt + 1], Ar[4 * kt + 2], Ar[4 * kt + 3],
                             bWu2[nt * 8 + kt * 2], bWu2[nt * 8 + kt * 2 + 1]);
                if (mt < 2) {
                    if (nlo) { rs0[nt * 2] += d0; rs0[nt * 2 + 1] += d1; }
                    if (nhi) { rs0[nt * 2] += d2; rs0[nt * 2 + 1] += d3; }
                } else {
                    if (nlo) { rs1[nt * 2] += d0; rs1[nt * 2 + 1] += d1; }
                    if (nhi) { rs1[nt * 2] += d2; rs1[nt * 2 + 1] += d3; }
                }
                if (plo) { psum[nt * 2] += d0; psum[nt * 2 + 1] += d1; }
                if (phi) { psum[nt * 2] += d2; psum[nt * 2 + 1] += d3; }
            }
        }

        // butterfly-reduce rs over gid lanes; gid 0 stores row i0, gid 1 stores row i1
        #pragma unroll
        for (int v = 0; v < 8; v++) {
            rs0[v] += __shfl_xor_sync(0xffffffffu, rs0[v], 4);
            rs0[v] += __shfl_xor_sync(0xffffffffu, rs0[v], 8);
            rs0[v] += __shfl_xor_sync(0xffffffffu, rs0[v], 16);
            rs1[v] += __shfl_xor_sync(0xffffffffu, rs1[v], 4);
            rs1[v] += __shfl_xor_sync(0xffffffffu, rs1[v], 8);
            rs1[v] += __shfl_xor_sync(0xffffffffu, rs1[v], 16);
        }
        if (gid == 0) {
            #pragma unroll
            for (int nt = 0; nt < 4; nt++) {
                srs[i0 * 33 + 8 * nt + 2 * tig]     = rs0[nt * 2];
                srs[i0 * 33 + 8 * nt + 2 * tig + 1] = rs0[nt * 2 + 1];
            }
        }
        if (gid == 1) {
            #pragma unroll
            for (int nt = 0; nt < 4; nt++) {
                srs[i1 * 33 + 8 * nt + 2 * tig]     = rs1[nt * 2];
                srs[i1 * 33 + 8 * nt + 2 * tig + 1] = rs1[nt * 2 + 1];
            }
        }
    }

    // pair-sum: butterfly then one atomic set per warp
    #pragma unroll
    for (int v = 0; v < 8; v++) {
        psum[v] += __shfl_xor_sync(0xffffffffu, psum[v], 4);
        psum[v] += __shfl_xor_sync(0xffffffffu, psum[v], 8);
        psum[v] += __shfl_xor_sync(0xffffffffu, psum[v], 16);
    }
    if (gid == 0) {
        #pragma unroll
        for (int nt = 0; nt < 4; nt++) {
            atomicAdd(&spair[8 * nt + 2 * tig],     psum[nt * 2]);
            atomicAdd(&spair[8 * nt + 2 * tig + 1], psum[nt * 2 + 1]);
        }
    }
    __syncthreads();

    // ---- m_v = We2v @ rowsum  (reuse sp) ----
    #pragma unroll
    for (int it = 0; it < 4; it++) {
        int h = w + it * 8;
        int i = lane;
        float a0 = 0.f, a1 = 0.f;
        #pragma unroll
        for (int c = 0; c < 32; c += 2) {
            a0 = fmaf(We2v[h * 32 + c + 0], srs[i * 33 + c + 0], a0);
            a1 = fmaf(We2v[h * 32 + c + 1], srs[i * 33 + c + 1], a1);
        }
        sp[i * 33 + h] = a0 + a1;
    }
    __syncthreads();

    // ---- a1 = silu(Wn1 @ [h_v, m_v] + bn1)  (reuse sq) ----
    #pragma unroll
    for (int it = 0; it < 4; it++) {
        int h = w + it * 8;
        int i = lane;
        float a = bn1[h];
        #pragma unroll
        for (int k = 0; k < 32; k++) a = fmaf(Wn1[h * 64 + k],      shv[i * 33 + k], a);
        #pragma unroll
        for (int k = 0; k < 32; k++) a = fmaf(Wn1[h * 64 + 32 + k], sp [i * 33 + k], a);
        sq[i * 34 + h] = silu_f(a);
    }
    __syncthreads();

    // ---- h_v_new = h_v + Wn2 @ a1 + bn2  (reuse ssj) ----
    #pragma unroll
    for (int it = 0; it < 4; it++) {
        int h = w + it * 8;
        int i = lane;
        float a = shv[i * 33 + h] + bn2[h];
        #pragma unroll
        for (int c = 0; c < 32; c++) a = fmaf(Wn2[h * 32 + c], sq[i * 34 + c], a);
        ssj[i * 34 + h] = a;
    }

    // ---- pairwise scalars ----
    float r2_l = 0.0f, s1_l = 0.0f, cusp_l = 0.0f;
    if (tid < 96) r2_l = sx[tid] * sx[tid];
    for (int idx = tid; idx < 496; idx += 256) {
        int rem = idx, pi = 0, cnt = 31;
        while (rem >= cnt) { rem -= cnt; pi++; cnt--; }
        int pj = pi + 1 + rem;
        float d0 = sx[pi * 3 + 0] - sx[pj * 3 + 0];
        float d1 = sx[pi * 3 + 1] - sx[pj * 3 + 1];
        float d2 = sx[pi * 3 + 2] - sx[pj * 3 + 2];
        float dd = fmaf(d0, d0, fmaf(d1, d1, d2 * d2));
        s1_l += log1pf((dd + 1e-8f) * 25.0f);
        float rc = sqrtf(dd + 1e-30f);
        bool same = (pi < 16) == (pj < 16);
        float gamma = same ? 0.25f : 0.5f;
        cusp_l += gamma * rc * __expf(-rc);
    }
    #pragma unroll
    for (int s = 16; s > 0; s >>= 1) {
        r2_l   += __shfl_xor_sync(0xffffffffu, r2_l,   s);
        s1_l   += __shfl_xor_sync(0xffffffffu, s1_l,   s);
        cusp_l += __shfl_xor_sync(0xffffffffu, cusp_l, s);
    }
    if (lane == 0) {
        atomicAdd(&sred[0], r2_l);
        atomicAdd(&sred[1], s1_l);
        atomicAdd(&sred[2], cusp_l);
    }
    __syncthreads();

    // ---- assemble f_in (130) ----
    if (tid < 32) {
        float hs = 0.0f;
        #pragma unroll
        for (int i2 = 0; i2 < 32; i2++) hs += ssj[i2 * 34 + tid];
        sfin[tid]      = hs;
        sfin[32 + tid] = hs * (1.0f / 32.0f);
        float ps = spair[tid];
        sfin[64 + tid] = ps;
        sfin[96 + tid] = ps * (1.0f / 496.0f);
    }
    if (tid == 0) {
        sfin[128] = sred[0] * (1.0f / 96.0f);
        sfin[129] = sred[1] * (1.0f / 496.0f);
        sfin[130] = 0.0f;  sfin[131] = 0.0f;
    }
    __syncthreads();

    // ---- readout: 130 -> 64 -> 64 -> 1 ----
    #pragma unroll 1
    for (int oo = 0; oo < 8; oo++) {
        int o = w * 8 + oo;
        float a = 0.0f;
        a = fmaf(Wf1[o * 130 + lane],      sfin[lane],      a);
        a = fmaf(Wf1[o * 130 + lane + 32], sfin[lane + 32], a);
        a = fmaf(Wf1[o * 130 + lane + 64], sfin[lane + 64], a);
        a = fmaf(Wf1[o * 130 + lane + 96], sfin[lane + 96], a);
        if (lane < 2) a = fmaf(Wf1[o * 130 + lane + 128], sfin[lane + 128], a);
        #pragma unroll
        for (int s = 16; s > 0; s >>= 1) a += __shfl_xor_sync(0xffffffffu, a, s);
        if (lane == 0) sf1[o] = silu_f(a + bf1[o]);
    }
    __syncthreads();

    #pragma unroll 1
    for (int oo = 0; oo < 8; oo++) {
        int o = w * 8 + oo;
        float a = fmaf(Wf2[o * 64 + lane],      sf1[lane],      0.0f);
        a       = fmaf(Wf2[o * 64 + lane + 32], sf1[lane + 32], a);
        #pragma unroll
        for (int s = 16; s > 0; s >>= 1) a += __shfl_xor_sync(0xffffffffu, a, s);
        if (lane == 0) sf2[o] = silu_f(a + bf2[o]);
    }
    __syncthreads();

    if (w == 0) {
        float a = fmaf(Wf3[lane],      sf2[lane],      0.0f);
        a       = fmaf(Wf3[lane + 32], sf2[lane + 32], a);
        #pragma unroll
        for (int s = 16; s > 0; s >>= 1) a += __shfl_xor_sync(0xffffffffu, a, s);
        if (lane == 0) out[b] = a + bf3[0] + sred[2];
    }
}

extern "C" void kernel_launch(void* const* d_in, const int* in_sizes, int n_in,
                              void* d_out, int out_size)
{
    const float* x      = (const float*)d_in[0];
    const float* W_node = (const float*)d_in[1];
    const float* b_node = (const float*)d_in[2];
    const float* We1    = (const float*)d_in[3];
    const float* be1    = (const float*)d_in[4];
    const float* We2    = (const float*)d_in[5];
    const float* be2    = (const float*)d_in[6];
    const float* Wv2e   = (const float*)d_in[7];
    const float* We2v   = (const float*)d_in[8];
    const float* Wu1    = (const float*)d_in[9];
    const float* bu1    = (const float*)d_in[10];
    const float* Wu2    = (const float*)d_in[11];
    const float* bu2    = (const float*)d_in[12];
    const float* Wn1    = (const float*)d_in[13];
    const float* bn1    = (const float*)d_in[14];
    const float* Wn2    = (const float*)d_in[15];
    const float* bn2    = (const float*)d_in[16];
    const float* Wf1    = (const float*)d_in[17];
    const float* bf1    = (const float*)d_in[18];
    const float* Wf2    = (const float*)d_in[19];
    const float* bf2    = (const float*)d_in[20];
    const float* Wf3    = (const float*)d_in[21];
    const float* bf3    = (const float*)d_in[22];

    const int dyn_smem = 8 * 2 * 64 * ST * (int)sizeof(float);   // 147456 B
    static bool attr_set = false;
    if (!attr_set) {
        cudaFuncSetAttribute(jastrow_kernel,
                             cudaFuncAttributeMaxDynamicSharedMemorySize, dyn_smem);
        attr_set = true;
    }

    int B = in_sizes[0] / 96;   // (B, 32, 3)
    jastrow_kernel<<<B, 256, dyn_smem>>>(x, W_node, b_node, We1, be1, We2, be2,
                                         Wv2e, We2v, Wu1, bu1, Wu2, bu2,
                                         Wn1, bn1, Wn2, bn2,
                                         Wf1, bf1, Wf2, bf2, Wf3, bf3,
                                         (float*)d_out);
}

// round 10
// speedup vs baseline: 1.3214x; 1.3214x over previous
#include <cuda_runtime.h>
#include <cstdint>

// CTNNBackflowStyleJastrow: B=1024, N=32, D=3, H=M=32, RH=64
// One CTA (256 threads = 8 warps) per batch element, 2 CTAs/SM.
// Round-8 structure (M=32 tf32 mma stages, smem readback reduction) with the
// weight B-fragments moved to a shared fragment table so regs fit 128
// (__launch_bounds__(256,2) -> 2 CTAs/SM -> 16 warps/SM latency hiding).

__device__ __forceinline__ float silu_f(float x) {
    return __fdividef(x, 1.0f + __expf(-x));
}
__device__ __forceinline__ uint32_t f2tf(float f) {
    uint32_t r; asm("cvt.rna.tf32.f32 %0, %1;" : "=r"(r) : "f"(f)); return r;
}
__device__ __forceinline__ float tfbits(float f) {
    return __uint_as_float(f2tf(f));
}
__device__ __forceinline__ void mma_tf32(float& d0, float& d1, float& d2, float& d3,
                                         uint32_t a0, uint32_t a1, uint32_t a2, uint32_t a3,
                                         uint32_t b0, uint32_t b1) {
    asm volatile("mma.sync.aligned.m16n8k8.row.col.f32.tf32.tf32.f32 "
                 "{%0,%1,%2,%3}, {%4,%5,%6,%7}, {%8,%9}, {%0,%1,%2,%3};"
                 : "+f"(d0), "+f"(d1), "+f"(d2), "+f"(d3)
                 : "r"(a0), "r"(a1), "r"(a2), "r"(a3), "r"(b0), "r"(b1));
}

#define ST 36   // buffer stride: A-frag loads conflict-free

__global__ __launch_bounds__(256, 2)
void jastrow_kernel(const float* __restrict__ x,
                    const float* __restrict__ W_node, const float* __restrict__ b_node,
                    const float* __restrict__ We1,  const float* __restrict__ be1,
                    const float* __restrict__ We2,  const float* __restrict__ be2,
                    const float* __restrict__ Wv2e, const float* __restrict__ We2v,
                    const float* __restrict__ Wu1,  const float* __restrict__ bu1,
                    const float* __restrict__ Wu2,  const float* __restrict__ bu2,
                    const float* __restrict__ Wn1,  const float* __restrict__ bn1,
                    const float* __restrict__ Wn2,  const float* __restrict__ bn2,
                    const float* __restrict__ Wf1,  const float* __restrict__ bf1,
                    const float* __restrict__ Wf2,  const float* __restrict__ bf2,
                    const float* __restrict__ Wf3,  const float* __restrict__ bf3,
                    float* __restrict__ out)
{
    __shared__ float sx[96];
    __shared__ float shv[32 * 33];
    __shared__ float sp [32 * 33];
    __shared__ __align__(8) float sq [32 * 34];
    __shared__ __align__(8) float ssj[32 * 34];
    __shared__ float srs[32 * 33];
    __shared__ __align__(8) float sbe1[32], sbe2[32], sbu2[32];
    __shared__ float spair[32];
    __shared__ float sred[3];
    __shared__ float sfin[132], sf1[64], sf2[64];
    // weight B-fragment tables: [pair][lane] float2 (b0,b1), conflict-free LDS.64
    __shared__ __align__(8) float2 sFe1[4 * 32];
    __shared__ __align__(8) float2 sFe2[16 * 32];
    __shared__ __align__(8) float2 sFu1[16 * 32];
    __shared__ __align__(8) float2 sFu2[16 * 32];
    extern __shared__ __align__(16) float dynsmem[];   // per warp: Tb[32*ST] + HE[32*ST]

    const int tid  = threadIdx.x;
    const int lane = tid & 31;
    const int w    = tid >> 5;
    const int b    = blockIdx.x;
    const int gid  = lane >> 2;
    const int tig  = lane & 3;

    // ---- stage inputs, biases, fragment tables ----
    if (tid < 96) sx[tid] = x[b * 96 + tid];
    if (tid < 32) {
        spair[tid] = 0.0f;
        sbe1[tid] = be1[tid]; sbe2[tid] = be2[tid]; sbu2[tid] = bu2[tid];
    }
    if (tid < 3)  sred[tid] = 0.0f;
    for (int idx = tid; idx < 4 * 32; idx += 256) {
        int pair = idx >> 5, ln = idx & 31;
        int g = ln >> 2, t = ln & 3;
        int n = 8 * pair + g;
        float b1v = (t == 0) ? tfbits(We1[n * 5 + 4]) : 0.0f;
        sFe1[idx] = make_float2(tfbits(We1[n * 5 + t]), b1v);
    }
    for (int idx = tid; idx < 16 * 32; idx += 256) {
        int pair = idx >> 5, ln = idx & 31;
        int nt = pair >> 2, kt = pair & 3;
        int g = ln >> 2, t = ln & 3;
        int n = 8 * nt + g, k = 8 * kt + t;
        sFe2[idx] = make_float2(tfbits(We2[n * 32 + k]), tfbits(We2[n * 32 + k + 4]));
        sFu1[idx] = make_float2(tfbits(Wu1[n * 96 + k]), tfbits(Wu1[n * 96 + k + 4]));
        sFu2[idx] = make_float2(tfbits(Wu2[n * 32 + k]), tfbits(Wu2[n * 32 + k + 4]));
    }
    __syncthreads();

    // ---- node phases ----
    #pragma unroll
    for (int it = 0; it < 4; it++) {
        int ch = w + it * 8;
        int i  = lane;
        float sf = (i >= 16) ? 1.0f : 0.0f;
        float a = b_node[ch]
                + W_node[ch * 4 + 0] * sx[i * 3 + 0]
                + W_node[ch * 4 + 1] * sx[i * 3 + 1]
                + W_node[ch * 4 + 2] * sx[i * 3 + 2]
                + W_node[ch * 4 + 3] * sf;
        shv[i * 33 + ch] = a;
    }
    __syncthreads();

    // p = h_v @ Wv2e^T
    #pragma unroll
    for (int it = 0; it < 4; it++) {
        int m = w + it * 8;
        int i = lane;
        float a0 = 0.f, a1 = 0.f;
        #pragma unroll
        for (int h = 0; h < 32; h += 2) {
            a0 = fmaf(Wv2e[m * 32 + h + 0], shv[i * 33 + h + 0], a0);
            a1 = fmaf(Wv2e[m * 32 + h + 1], shv[i * 33 + h + 1], a1);
        }
        sp[i * 33 + m] = a0 + a1;
    }
    __syncthreads();

    // q_i, s_j
    #pragma unroll
    for (int it = 0; it < 4; it++) {
        int h = w + it * 8;
        int i = lane;
        float aq = bu1[h], as = 0.f;
        #pragma unroll
        for (int m = 0; m < 32; m++) {
            float pv = sp[i * 33 + m];
            aq = fmaf(Wu1[h * 96 + 32 + m], pv, aq);
            as = fmaf(Wu1[h * 96 + 64 + m], pv, as);
        }
        sq [i * 34 + h] = aq;
        ssj[i * 34 + h] = as;
    }
    __syncthreads();

    // ---- edge loop: warp w owns rows i = 4w..4w+3; GEMM per stage ----
    float* Tb = dynsmem + w * (2 * 32 * ST);
    float* HE = Tb + 32 * ST;
    float* F  = HE;                    // stage-1 feature scratch aliases HE (stride 12)

    const float xj0 = sx[lane * 3 + 0], xj1 = sx[lane * 3 + 1], xj2 = sx[lane * 3 + 2];
    float pacc = 0.0f;

    #pragma unroll 1
    for (int ii = 0; ii < 4; ii++) {
        const int i = w * 4 + ii;

        // features (lane = edge j)
        {
            float fr0 = sx[i * 3 + 0] - xj0;
            float fr1 = sx[i * 3 + 1] - xj1;
            float fr2 = sx[i * 3 + 2] - xj2;
            float rr2 = fmaf(fr0, fr0, fmaf(fr1, fr1, fr2 * fr2));
            float tpl = rr2 + 1e-12f;
            float rr1 = tpl * __frsqrt_rn(tpl);
            __syncwarp();   // prior iter's reduction reads of HE done
            *reinterpret_cast<float4*>(&F[lane * 12]) =
                make_float4(tfbits(fr0), tfbits(fr1), tfbits(fr2), tfbits(rr1));
            *reinterpret_cast<float4*>(&F[lane * 12 + 4]) =
                make_float4(tfbits(rr2), 0.0f, 0.0f, 0.0f);
            __syncwarp();
        }

        // stage 1: T = silu(F @ We1^T + be1)   (K=8, 1 K-tile)
        #pragma unroll
        for (int mt = 0; mt < 2; mt++) {
            uint32_t A0 = __float_as_uint(F[(16 * mt + gid) * 12 + tig]);
            uint32_t A1 = __float_as_uint(F[(16 * mt + gid + 8) * 12 + tig]);
            uint32_t A2 = __float_as_uint(F[(16 * mt + gid) * 12 + tig + 4]);
            uint32_t A3 = __float_as_uint(F[(16 * mt + gid + 8) * 12 + tig + 4]);
            #pragma unroll
            for (int nt = 0; nt < 4; nt++) {
                int col = 8 * nt + 2 * tig;
                float2 bb = *reinterpret_cast<const float2*>(&sbe1[col]);
                float2 wv = sFe1[nt * 32 + lane];
                float d0 = bb.x, d1 = bb.y, d2 = bb.x, d3 = bb.y;
                mma_tf32(d0, d1, d2, d3, A0, A1, A2, A3,
                         __float_as_uint(wv.x), __float_as_uint(wv.y));
                int r0 = (16 * mt + gid) * ST + col;
                *reinterpret_cast<float2*>(&Tb[r0]) =
                    make_float2(tfbits(silu_f(d0)), tfbits(silu_f(d1)));
                *reinterpret_cast<float2*>(&Tb[r0 + 8 * ST]) =
                    make_float2(tfbits(silu_f(d2)), tfbits(silu_f(d3)));
            }
        }
        __syncwarp();

        // stage 2: HE = T @ We2^T + be2
        #pragma unroll
        for (int mt = 0; mt < 2; mt++) {
            uint32_t Ar[16];
            #pragma unroll
            for (int kt = 0; kt < 4; kt++) {
                const float* p0 = &Tb[(16 * mt + gid) * ST + 8 * kt + tig];
                const float* p1 = &Tb[(16 * mt + gid + 8) * ST + 8 * kt + tig];
                Ar[4 * kt + 0] = __float_as_uint(p0[0]);
                Ar[4 * kt + 1] = __float_as_uint(p1[0]);
                Ar[4 * kt + 2] = __float_as_uint(p0[4]);
                Ar[4 * kt + 3] = __float_as_uint(p1[4]);
            }
            #pragma unroll
            for (int nt = 0; nt < 4; nt++) {
                int col = 8 * nt + 2 * tig;
                float2 bb = *reinterpret_cast<const float2*>(&sbe2[col]);
                float d0 = bb.x, d1 = bb.y, d2 = bb.x, d3 = bb.y;
                #pragma unroll
                for (int kt = 0; kt < 4; kt++) {
                    float2 wv = sFe2[(nt * 4 + kt) * 32 + lane];
                    mma_tf32(d0, d1, d2, d3,
                             Ar[4 * kt + 0], Ar[4 * kt + 1], Ar[4 * kt + 2], Ar[4 * kt + 3],
                             __float_as_uint(wv.x), __float_as_uint(wv.y));
                }
                int r0 = (16 * mt + gid) * ST + col;
                *reinterpret_cast<float2*>(&HE[r0]) = make_float2(tfbits(d0), tfbits(d1));
                *reinterpret_cast<float2*>(&HE[r0 + 8 * ST]) = make_float2(tfbits(d2), tfbits(d3));
            }
        }
        __syncwarp();

        // stage 3: T = silu(HE @ Wu1a^T + q_i[col] + s_j[row][col])
        #pragma unroll
        for (int mt = 0; mt < 2; mt++) {
            uint32_t Ar[16];
            #pragma unroll
            for (int kt = 0; kt < 4; kt++) {
                const float* p0 = &HE[(16 * mt + gid) * ST + 8 * kt + tig];
                const float* p1 = &HE[(16 * mt + gid + 8) * ST + 8 * kt + tig];
                Ar[4 * kt + 0] = __float_as_uint(p0[0]);
                Ar[4 * kt + 1] = __float_as_uint(p1[0]);
                Ar[4 * kt + 2] = __float_as_uint(p0[4]);
                Ar[4 * kt + 3] = __float_as_uint(p1[4]);
            }
            #pragma unroll
            for (int nt = 0; nt < 4; nt++) {
                int col = 8 * nt + 2 * tig;
                float2 qv = *reinterpret_cast<const float2*>(&sq[i * 34 + col]);
                float2 s0 = *reinterpret_cast<const float2*>(&ssj[(16 * mt + gid) * 34 + col]);
                float2 s1 = *reinterpret_cast<const float2*>(&ssj[(16 * mt + gid + 8) * 34 + col]);
                float d0 = qv.x + s0.x, d1 = qv.y + s0.y;
                float d2 = qv.x + s1.x, d3 = qv.y + s1.y;
                #pragma unroll
                for (int kt = 0; kt < 4; kt++) {
                    float2 wv = sFu1[(nt * 4 + kt) * 32 + lane];
                    mma_tf32(d0, d1, d2, d3,
                             Ar[4 * kt + 0], Ar[4 * kt + 1], Ar[4 * kt + 2], Ar[4 * kt + 3],
                             __float_as_uint(wv.x), __float_as_uint(wv.y));
                }
                int r0 = (16 * mt + gid) * ST + col;
                *reinterpret_cast<float2*>(&Tb[r0]) =
                    make_float2(tfbits(silu_f(d0)), tfbits(silu_f(d1)));
                *reinterpret_cast<float2*>(&Tb[r0 + 8 * ST]) =
                    make_float2(tfbits(silu_f(d2)), tfbits(silu_f(d3)));
            }
        }
        __syncwarp();

        // stage 4: T = T @ Wu2^T + bu2   (in-place, tile loads precede stores)
        #pragma unroll
        for (int mt = 0; mt < 2; mt++) {
            uint32_t Ar[16];
            #pragma unroll
            for (int kt = 0; kt < 4; kt++) {
                const float* p0 = &Tb[(16 * mt + gid) * ST + 8 * kt + tig];
                const float* p1 = &Tb[(16 * mt + gid + 8) * ST + 8 * kt + tig];
                Ar[4 * kt + 0] = __float_as_uint(p0[0]);
                Ar[4 * kt + 1] = __float_as_uint(p1[0]);
                Ar[4 * kt + 2] = __float_as_uint(p0[4]);
                Ar[4 * kt + 3] = __float_as_uint(p1[4]);
            }
            __syncwarp();
            #pragma unroll
            for (int nt = 0; nt < 4; nt++) {
                int col = 8 * nt + 2 * tig;
                float2 bb = *reinterpret_cast<const float2*>(&sbu2[col]);
                float d0 = bb.x, d1 = bb.y, d2 = bb.x, d3 = bb.y;
                #pragma unroll
                for (int kt = 0; kt < 4; kt++) {
                    float2 wv = sFu2[(nt * 4 + kt) * 32 + lane];
                    mma_tf32(d0, d1, d2, d3,
                             Ar[4 * kt + 0], Ar[4 * kt + 1], Ar[4 * kt + 2], Ar[4 * kt + 3],
                             __float_as_uint(wv.x), __float_as_uint(wv.y));
                }
                int r0 = (16 * mt + gid) * ST + col;
                *reinterpret_cast<float2*>(&Tb[r0]) = make_float2(d0, d1);
                *reinterpret_cast<float2*>(&Tb[r0 + 8 * ST]) = make_float2(d2, d3);
            }
        }
        __syncwarp();

        // reduction: lane = channel c (smem readback, round-8 style)
        {
            float rsum = 0.0f, psum = 0.0f;
            #pragma unroll
            for (int jj = 0; jj < 32; jj++) {
                float hn = Tb[jj * ST + lane];
                float he = HE[jj * ST + lane];
                rsum += hn;
                float mk = (jj > i) ? 1.0f : 0.0f;
                psum = fmaf(mk, hn + he, psum);
            }
            rsum -= Tb[i * ST + lane];
            srs[i * 33 + lane] = rsum;
            pacc += psum;
        }
    }
    atomicAdd(&spair[lane], pacc);
    __syncthreads();

    // ---- m_v = We2v @ rowsum  (reuse sp) ----
    #pragma unroll
    for (int it = 0; it < 4; it++) {
        int h = w + it * 8;
        int i = lane;
        float a0 = 0.f, a1 = 0.f;
        #pragma unroll
        for (int c = 0; c < 32; c += 2) {
            a0 = fmaf(We2v[h * 32 + c + 0], srs[i * 33 + c + 0], a0);
            a1 = fmaf(We2v[h * 32 + c + 1], srs[i * 33 + c + 1], a1);
        }
        sp[i * 33 + h] = a0 + a1;
    }
    __syncthreads();

    // ---- a1 = silu(Wn1 @ [h_v, m_v] + bn1)  (reuse sq) ----
    #pragma unroll
    for (int it = 0; it < 4; it++) {
        int h = w + it * 8;
        int i = lane;
        float a = bn1[h];
        #pragma unroll
        for (int k = 0; k < 32; k++) a = fmaf(Wn1[h * 64 + k],      shv[i * 33 + k], a);
        #pragma unroll
        for (int k = 0; k < 32; k++) a = fmaf(Wn1[h * 64 + 32 + k], sp [i * 33 + k], a);
        sq[i * 34 + h] = silu_f(a);
    }
    __syncthreads();

    // ---- h_v_new = h_v + Wn2 @ a1 + bn2  (reuse ssj) ----
    #pragma unroll
    for (int it = 0; it < 4; it++) {
        int h = w + it * 8;
        int i = lane;
        float a = shv[i * 33 + h] + bn2[h];
        #pragma unroll
        for (int c = 0; c < 32; c++) a = fmaf(Wn2[h * 32 + c], sq[i * 34 + c], a);
        ssj[i * 34 + h] = a;
    }

    // ---- pairwise scalars ----
    float r2_l = 0.0f, s1_l = 0.0f, cusp_l = 0.0f;
    if (tid < 96) r2_l = sx[tid] * sx[tid];
    for (int idx = tid; idx < 496; idx += 256) {
        int rem = idx, pi = 0, cnt = 31;
        while (rem >= cnt) { rem -= cnt; pi++; cnt--; }
        int pj = pi + 1 + rem;
        float d0 = sx[pi * 3 + 0] - sx[pj * 3 + 0];
        float d1 = sx[pi * 3 + 1] - sx[pj * 3 + 1];
        float d2 = sx[pi * 3 + 2] - sx[pj * 3 + 2];
        float dd = fmaf(d0, d0, fmaf(d1, d1, d2 * d2));
        s1_l += log1pf((dd + 1e-8f) * 25.0f);
        float rc = sqrtf(dd + 1e-30f);
        bool same = (pi < 16) == (pj < 16);
        float gamma = same ? 0.25f : 0.5f;
        cusp_l += gamma * rc * __expf(-rc);
    }
    #pragma unroll
    for (int s = 16; s > 0; s >>= 1) {
        r2_l   += __shfl_xor_sync(0xffffffffu, r2_l,   s);
        s1_l   += __shfl_xor_sync(0xffffffffu, s1_l,   s);
        cusp_l += __shfl_xor_sync(0xffffffffu, cusp_l, s);
    }
    if (lane == 0) {
        atomicAdd(&sred[0], r2_l);
        atomicAdd(&sred[1], s1_l);
        atomicAdd(&sred[2], cusp_l);
    }
    __syncthreads();

    // ---- assemble f_in (130) ----
    if (tid < 32) {
        float hs = 0.0f;
        #pragma unroll
        for (int i2 = 0; i2 < 32; i2++) hs += ssj[i2 * 34 + tid];
        sfin[tid]      = hs;
        sfin[32 + tid] = hs * (1.0f / 32.0f);
        float ps = spair[tid];
        sfin[64 + tid] = ps;
        sfin[96 + tid] = ps * (1.0f / 496.0f);
    }
    if (tid == 0) {
        sfin[128] = sred[0] * (1.0f / 96.0f);
        sfin[129] = sred[1] * (1.0f / 496.0f);
        sfin[130] = 0.0f;  sfin[131] = 0.0f;
    }
    __syncthreads();

    // ---- readout: 130 -> 64 -> 64 -> 1 ----
    #pragma unroll 1
    for (int oo = 0; oo < 8; oo++) {
        int o = w * 8 + oo;
        float a = 0.0f;
        a = fmaf(Wf1[o * 130 + lane],      sfin[lane],      a);
        a = fmaf(Wf1[o * 130 + lane + 32], sfin[lane + 32], a);
        a = fmaf(Wf1[o * 130 + lane + 64], sfin[lane + 64], a);
        a = fmaf(Wf1[o * 130 + lane + 96], sfin[lane + 96], a);
        if (lane < 2) a = fmaf(Wf1[o * 130 + lane + 128], sfin[lane + 128], a);
        #pragma unroll
        for (int s = 16; s > 0; s >>= 1) a += __shfl_xor_sync(0xffffffffu, a, s);
        if (lane == 0) sf1[o] = silu_f(a + bf1[o]);
    }
    __syncthreads();

    #pragma unroll 1
    for (int oo = 0; oo < 8; oo++) {
        int o = w * 8 + oo;
        float a = fmaf(Wf2[o * 64 + lane],      sf1[lane],      0.0f);
        a       = fmaf(Wf2[o * 64 + lane + 32], sf1[lane + 32], a);
        #pragma unroll
        for (int s = 16; s > 0; s >>= 1) a += __shfl_xor_sync(0xffffffffu, a, s);
        if (lane == 0) sf2[o] = silu_f(a + bf2[o]);
    }
    __syncthreads();

    if (w == 0) {
        float a = fmaf(Wf3[lane],      sf2[lane],      0.0f);
        a       = fmaf(Wf3[lane + 32], sf2[lane + 32], a);
        #pragma unroll
        for (int s = 16; s > 0; s >>= 1) a += __shfl_xor_sync(0xffffffffu, a, s);
        if (lane == 0) out[b] = a + bf3[0] + sred[2];
    }
}

extern "C" void kernel_launch(void* const* d_in, const int* in_sizes, int n_in,
                              void* d_out, int out_size)
{
    const float* x      = (const float*)d_in[0];
    const float* W_node = (const float*)d_in[1];
    const float* b_node = (const float*)d_in[2];
    const float* We1    = (const float*)d_in[3];
    const float* be1    = (const float*)d_in[4];
    const float* We2    = (const float*)d_in[5];
    const float* be2    = (const float*)d_in[6];
    const float* Wv2e   = (const float*)d_in[7];
    const float* We2v   = (const float*)d_in[8];
    const float* Wu1    = (const float*)d_in[9];
    const float* bu1    = (const float*)d_in[10];
    const float* Wu2    = (const float*)d_in[11];
    const float* bu2    = (const float*)d_in[12];
    const float* Wn1    = (const float*)d_in[13];
    const float* bn1    = (const float*)d_in[14];
    const float* Wn2    = (const float*)d_in[15];
    const float* bn2    = (const float*)d_in[16];
    const float* Wf1    = (const float*)d_in[17];
    const float* bf1    = (const float*)d_in[18];
    const float* Wf2    = (const float*)d_in[19];
    const float* bf2    = (const float*)d_in[20];
    const float* Wf3    = (const float*)d_in[21];
    const float* bf3    = (const float*)d_in[22];

    const int dyn_smem = 8 * 2 * 32 * ST * (int)sizeof(float);   // 73728 B
    static bool attr_set = false;
    if (!attr_set) {
        cudaFuncSetAttribute(jastrow_kernel,
                             cudaFuncAttributeMaxDynamicSharedMemorySize, dyn_smem);
        attr_set = true;
    }

    int B = in_sizes[0] / 96;   // (B, 32, 3)
    jastrow_kernel<<<B, 256, dyn_smem>>>(x, W_node, b_node, We1, be1, We2, be2,
                                         Wv2e, We2v, Wu1, bu1, Wu2, bu2,
                                         Wn1, bn1, Wn2, bn2,
                                         Wf1, bf1, Wf2, bf2, Wf3, bf3,
                                         (float*)d_out);
}

// round 11
// speedup vs baseline: 1.4621x; 1.1065x over previous
#include <cuda_runtime.h>
#include <cstdint>

// CTNNBackflowStyleJastrow: B=1024, N=32, D=3, H=M=32, RH=64
// One CTA (256 threads = 8 warps) per batch element, 2 CTAs/SM.
// tf32 mma edge loop with shared weight-fragment tables; weights/biases for
// each stage hoisted into registers across the mt loop (halves table LDS).

__device__ __forceinline__ float silu_f(float x) {
    return __fdividef(x, 1.0f + __expf(-x));
}
__device__ __forceinline__ uint32_t f2tf(float f) {
    uint32_t r; asm("cvt.rna.tf32.f32 %0, %1;" : "=r"(r) : "f"(f)); return r;
}
__device__ __forceinline__ float tfbits(float f) {
    return __uint_as_float(f2tf(f));
}
__device__ __forceinline__ void mma_tf32(float& d0, float& d1, float& d2, float& d3,
                                         uint32_t a0, uint32_t a1, uint32_t a2, uint32_t a3,
                                         uint32_t b0, uint32_t b1) {
    asm volatile("mma.sync.aligned.m16n8k8.row.col.f32.tf32.tf32.f32 "
                 "{%0,%1,%2,%3}, {%4,%5,%6,%7}, {%8,%9}, {%0,%1,%2,%3};"
                 : "+f"(d0), "+f"(d1), "+f"(d2), "+f"(d3)
                 : "r"(a0), "r"(a1), "r"(a2), "r"(a3), "r"(b0), "r"(b1));
}

#define ST 36   // buffer stride: A-frag loads conflict-free

__global__ __launch_bounds__(256, 2)
void jastrow_kernel(const float* __restrict__ x,
                    const float* __restrict__ W_node, const float* __restrict__ b_node,
                    const float* __restrict__ We1,  const float* __restrict__ be1,
                    const float* __restrict__ We2,  const float* __restrict__ be2,
                    const float* __restrict__ Wv2e, const float* __restrict__ We2v,
                    const float* __restrict__ Wu1,  const float* __restrict__ bu1,
                    const float* __restrict__ Wu2,  const float* __restrict__ bu2,
                    const float* __restrict__ Wn1,  const float* __restrict__ bn1,
                    const float* __restrict__ Wn2,  const float* __restrict__ bn2,
                    const float* __restrict__ Wf1,  const float* __restrict__ bf1,
                    const float* __restrict__ Wf2,  const float* __restrict__ bf2,
                    const float* __restrict__ Wf3,  const float* __restrict__ bf3,
                    float* __restrict__ out)
{
    __shared__ float sx[96];
    __shared__ float shv[32 * 33];
    __shared__ float sp [32 * 33];
    __shared__ __align__(8) float sq [32 * 34];
    __shared__ __align__(8) float ssj[32 * 34];
    __shared__ float srs[32 * 33];
    __shared__ __align__(8) float sbe1[32], sbe2[32], sbu2[32];
    __shared__ float spair[32];
    __shared__ float sred[3];
    __shared__ float sfin[132], sf1[64], sf2[64];
    // weight B-fragment tables: [pair][lane] float2 (b0,b1)
    __shared__ __align__(8) float2 sFe1[4 * 32];
    __shared__ __align__(8) float2 sFe2[16 * 32];
    __shared__ __align__(8) float2 sFu1[16 * 32];
    __shared__ __align__(8) float2 sFu2[16 * 32];
    extern __shared__ __align__(16) float dynsmem[];   // per warp: Tb[32*ST] + HE[32*ST]

    const int tid  = threadIdx.x;
    const int lane = tid & 31;
    const int w    = tid >> 5;
    const int b    = blockIdx.x;
    const int gid  = lane >> 2;
    const int tig  = lane & 3;

    // ---- stage inputs, biases, fragment tables ----
    if (tid < 96) sx[tid] = x[b * 96 + tid];
    if (tid < 32) {
        spair[tid] = 0.0f;
        sbe1[tid] = be1[tid]; sbe2[tid] = be2[tid]; sbu2[tid] = bu2[tid];
    }
    if (tid < 3)  sred[tid] = 0.0f;
    for (int idx = tid; idx < 4 * 32; idx += 256) {
        int pair = idx >> 5, ln = idx & 31;
        int g = ln >> 2, t = ln & 3;
        int n = 8 * pair + g;
        float b1v = (t == 0) ? tfbits(We1[n * 5 + 4]) : 0.0f;
        sFe1[idx] = make_float2(tfbits(We1[n * 5 + t]), b1v);
    }
    for (int idx = tid; idx < 16 * 32; idx += 256) {
        int pair = idx >> 5, ln = idx & 31;
        int nt = pair >> 2, kt = pair & 3;
        int g = ln >> 2, t = ln & 3;
        int n = 8 * nt + g, k = 8 * kt + t;
        sFe2[idx] = make_float2(tfbits(We2[n * 32 + k]), tfbits(We2[n * 32 + k + 4]));
        sFu1[idx] = make_float2(tfbits(Wu1[n * 96 + k]), tfbits(Wu1[n * 96 + k + 4]));
        sFu2[idx] = make_float2(tfbits(Wu2[n * 32 + k]), tfbits(Wu2[n * 32 + k + 4]));
    }
    __syncthreads();

    // ---- node phases ----
    #pragma unroll
    for (int it = 0; it < 4; it++) {
        int ch = w + it * 8;
        int i  = lane;
        float sf = (i >= 16) ? 1.0f : 0.0f;
        float a = b_node[ch]
                + W_node[ch * 4 + 0] * sx[i * 3 + 0]
                + W_node[ch * 4 + 1] * sx[i * 3 + 1]
                + W_node[ch * 4 + 2] * sx[i * 3 + 2]
                + W_node[ch * 4 + 3] * sf;
        shv[i * 33 + ch] = a;
    }
    __syncthreads();

    // p = h_v @ Wv2e^T
    #pragma unroll
    for (int it = 0; it < 4; it++) {
        int m = w + it * 8;
        int i = lane;
        float a0 = 0.f, a1 = 0.f;
        #pragma unroll
        for (int h = 0; h < 32; h += 2) {
            a0 = fmaf(Wv2e[m * 32 + h + 0], shv[i * 33 + h + 0], a0);
            a1 = fmaf(Wv2e[m * 32 + h + 1], shv[i * 33 + h + 1], a1);
        }
        sp[i * 33 + m] = a0 + a1;
    }
    __syncthreads();

    // q_i, s_j
    #pragma unroll
    for (int it = 0; it < 4; it++) {
        int h = w + it * 8;
        int i = lane;
        float aq = bu1[h], as = 0.f;
        #pragma unroll
        for (int m = 0; m < 32; m++) {
            float pv = sp[i * 33 + m];
            aq = fmaf(Wu1[h * 96 + 32 + m], pv, aq);
            as = fmaf(Wu1[h * 96 + 64 + m], pv, as);
        }
        sq [i * 34 + h] = aq;
        ssj[i * 34 + h] = as;
    }
    __syncthreads();

    // ---- edge loop: warp w owns rows i = 4w..4w+3; GEMM per stage ----
    float* Tb = dynsmem + w * (2 * 32 * ST);
    float* HE = Tb + 32 * ST;
    float* F  = HE;                    // stage-1 feature scratch aliases HE (stride 12)

    const float xj0 = sx[lane * 3 + 0], xj1 = sx[lane * 3 + 1], xj2 = sx[lane * 3 + 2];
    float pacc = 0.0f;

    #pragma unroll 1
    for (int ii = 0; ii < 4; ii++) {
        const int i = w * 4 + ii;

        // features (lane = edge j)
        {
            float fr0 = sx[i * 3 + 0] - xj0;
            float fr1 = sx[i * 3 + 1] - xj1;
            float fr2 = sx[i * 3 + 2] - xj2;
            float rr2 = fmaf(fr0, fr0, fmaf(fr1, fr1, fr2 * fr2));
            float tpl = rr2 + 1e-12f;
            float rr1 = tpl * __frsqrt_rn(tpl);
            __syncwarp();   // prior iter's reduction reads of HE done
            *reinterpret_cast<float4*>(&F[lane * 12]) =
                make_float4(tfbits(fr0), tfbits(fr1), tfbits(fr2), tfbits(rr1));
            *reinterpret_cast<float4*>(&F[lane * 12 + 4]) =
                make_float4(tfbits(rr2), 0.0f, 0.0f, 0.0f);
            __syncwarp();
        }

        // stage 1: T = silu(F @ We1^T + be1)   (K=8, 1 K-tile)
        {
            float2 wv[4], bb[4];
            #pragma unroll
            for (int nt = 0; nt < 4; nt++) {
                wv[nt] = sFe1[nt * 32 + lane];
                bb[nt] = *reinterpret_cast<const float2*>(&sbe1[8 * nt + 2 * tig]);
            }
            #pragma unroll
            for (int mt = 0; mt < 2; mt++) {
                uint32_t A0 = __float_as_uint(F[(16 * mt + gid) * 12 + tig]);
                uint32_t A1 = __float_as_uint(F[(16 * mt + gid + 8) * 12 + tig]);
                uint32_t A2 = __float_as_uint(F[(16 * mt + gid) * 12 + tig + 4]);
                uint32_t A3 = __float_as_uint(F[(16 * mt + gid + 8) * 12 + tig + 4]);
                #pragma unroll
                for (int nt = 0; nt < 4; nt++) {
                    int col = 8 * nt + 2 * tig;
                    float d0 = bb[nt].x, d1 = bb[nt].y, d2 = bb[nt].x, d3 = bb[nt].y;
                    mma_tf32(d0, d1, d2, d3, A0, A1, A2, A3,
                             __float_as_uint(wv[nt].x), __float_as_uint(wv[nt].y));
                    int r0 = (16 * mt + gid) * ST + col;
                    *reinterpret_cast<float2*>(&Tb[r0]) =
                        make_float2(tfbits(silu_f(d0)), tfbits(silu_f(d1)));
                    *reinterpret_cast<float2*>(&Tb[r0 + 8 * ST]) =
                        make_float2(tfbits(silu_f(d2)), tfbits(silu_f(d3)));
                }
            }
        }
        __syncwarp();

        // stage 2: HE = T @ We2^T + be2
        {
            float2 wv[16], bb[4];
            #pragma unroll
            for (int nt = 0; nt < 4; nt++) {
                bb[nt] = *reinterpret_cast<const float2*>(&sbe2[8 * nt + 2 * tig]);
                #pragma unroll
                for (int kt = 0; kt < 4; kt++)
                    wv[nt * 4 + kt] = sFe2[(nt * 4 + kt) * 32 + lane];
            }
            #pragma unroll
            for (int mt = 0; mt < 2; mt++) {
                uint32_t Ar[16];
                #pragma unroll
                for (int kt = 0; kt < 4; kt++) {
                    const float* p0 = &Tb[(16 * mt + gid) * ST + 8 * kt + tig];
                    const float* p1 = &Tb[(16 * mt + gid + 8) * ST + 8 * kt + tig];
                    Ar[4 * kt + 0] = __float_as_uint(p0[0]);
                    Ar[4 * kt + 1] = __float_as_uint(p1[0]);
                    Ar[4 * kt + 2] = __float_as_uint(p0[4]);
                    Ar[4 * kt + 3] = __float_as_uint(p1[4]);
                }
                #pragma unroll
                for (int nt = 0; nt < 4; nt++) {
                    int col = 8 * nt + 2 * tig;
                    float d0 = bb[nt].x, d1 = bb[nt].y, d2 = bb[nt].x, d3 = bb[nt].y;
                    #pragma unroll
                    for (int kt = 0; kt < 4; kt++)
                        mma_tf32(d0, d1, d2, d3,
                                 Ar[4 * kt + 0], Ar[4 * kt + 1], Ar[4 * kt + 2], Ar[4 * kt + 3],
                                 __float_as_uint(wv[nt * 4 + kt].x),
                                 __float_as_uint(wv[nt * 4 + kt].y));
                    int r0 = (16 * mt + gid) * ST + col;
                    *reinterpret_cast<float2*>(&HE[r0]) = make_float2(tfbits(d0), tfbits(d1));
                    *reinterpret_cast<float2*>(&HE[r0 + 8 * ST]) = make_float2(tfbits(d2), tfbits(d3));
                }
            }
        }
        __syncwarp();

        // stage 3: T = silu(HE @ Wu1a^T + q_i[col] + s_j[row][col])
        {
            float2 wv[16], qv[4];
            #pragma unroll
            for (int nt = 0; nt < 4; nt++) {
                qv[nt] = *reinterpret_cast<const float2*>(&sq[i * 34 + 8 * nt + 2 * tig]);
                #pragma unroll
                for (int kt = 0; kt < 4; kt++)
                    wv[nt * 4 + kt] = sFu1[(nt * 4 + kt) * 32 + lane];
            }
            #pragma unroll
            for (int mt = 0; mt < 2; mt++) {
                uint32_t Ar[16];
                #pragma unroll
                for (int kt = 0; kt < 4; kt++) {
                    const float* p0 = &HE[(16 * mt + gid) * ST + 8 * kt + tig];
                    const float* p1 = &HE[(16 * mt + gid + 8) * ST + 8 * kt + tig];
                    Ar[4 * kt + 0] = __float_as_uint(p0[0]);
                    Ar[4 * kt + 1] = __float_as_uint(p1[0]);
                    Ar[4 * kt + 2] = __float_as_uint(p0[4]);
                    Ar[4 * kt + 3] = __float_as_uint(p1[4]);
                }
                #pragma unroll
                for (int nt = 0; nt < 4; nt++) {
                    int col = 8 * nt + 2 * tig;
                    float2 s0 = *reinterpret_cast<const float2*>(&ssj[(16 * mt + gid) * 34 + col]);
                    float2 s1 = *reinterpret_cast<const float2*>(&ssj[(16 * mt + gid + 8) * 34 + col]);
                    float d0 = qv[nt].x + s0.x, d1 = qv[nt].y + s0.y;
                    float d2 = qv[nt].x + s1.x, d3 = qv[nt].y + s1.y;
                    #pragma unroll
                    for (int kt = 0; kt < 4; kt++)
                        mma_tf32(d0, d1, d2, d3,
                                 Ar[4 * kt + 0], Ar[4 * kt + 1], Ar[4 * kt + 2], Ar[4 * kt + 3],
                                 __float_as_uint(wv[nt * 4 + kt].x),
                                 __float_as_uint(wv[nt * 4 + kt].y));
                    int r0 = (16 * mt + gid) * ST + col;
                    *reinterpret_cast<float2*>(&Tb[r0]) =
                        make_float2(tfbits(silu_f(d0)), tfbits(silu_f(d1)));
                    *reinterpret_cast<float2*>(&Tb[r0 + 8 * ST]) =
                        make_float2(tfbits(silu_f(d2)), tfbits(silu_f(d3)));
                }
            }
        }
        __syncwarp();

        // stage 4: T = T @ Wu2^T + bu2   (in-place, tile loads precede stores)
        {
            float2 wv[16], bb[4];
            #pragma unroll
            for (int nt = 0; nt < 4; nt++) {
                bb[nt] = *reinterpret_cast<const float2*>(&sbu2[8 * nt + 2 * tig]);
                #pragma unroll
                for (int kt = 0; kt < 4; kt++)
                    wv[nt * 4 + kt] = sFu2[(nt * 4 + kt) * 32 + lane];
            }
            #pragma unroll
            for (int mt = 0; mt < 2; mt++) {
                uint32_t Ar[16];
                #pragma unroll
                for (int kt = 0; kt < 4; kt++) {
                    const float* p0 = &Tb[(16 * mt + gid) * ST + 8 * kt + tig];
                    const float* p1 = &Tb[(16 * mt + gid + 8) * ST + 8 * kt + tig];
                    Ar[4 * kt + 0] = __float_as_uint(p0[0]);
                    Ar[4 * kt + 1] = __float_as_uint(p1[0]);
                    Ar[4 * kt + 2] = __float_as_uint(p0[4]);
                    Ar[4 * kt + 3] = __float_as_uint(p1[4]);
                }
                __syncwarp();
                #pragma unroll
                for (int nt = 0; nt < 4; nt++) {
                    int col = 8 * nt + 2 * tig;
                    float d0 = bb[nt].x, d1 = bb[nt].y, d2 = bb[nt].x, d3 = bb[nt].y;
                    #pragma unroll
                    for (int kt = 0; kt < 4; kt++)
                        mma_tf32(d0, d1, d2, d3,
                                 Ar[4 * kt + 0], Ar[4 * kt + 1], Ar[4 * kt + 2], Ar[4 * kt + 3],
                                 __float_as_uint(wv[nt * 4 + kt].x),
                                 __float_as_uint(wv[nt * 4 + kt].y));
                    int r0 = (16 * mt + gid) * ST + col;
                    *reinterpret_cast<float2*>(&Tb[r0]) = make_float2(d0, d1);
                    *reinterpret_cast<float2*>(&Tb[r0 + 8 * ST]) = make_float2(d2, d3);
                }
            }
        }
        __syncwarp();

        // reduction: lane = channel c (smem readback)
        {
            float rsum = 0.0f, psum = 0.0f;
            #pragma unroll
            for (int jj = 0; jj < 32; jj++) {
                float hn = Tb[jj * ST + lane];
                float he = HE[jj * ST + lane];
                rsum += hn;
                float mk = (jj > i) ? 1.0f : 0.0f;
                psum = fmaf(mk, hn + he, psum);
            }
            rsum -= Tb[i * ST + lane];
            srs[i * 33 + lane] = rsum;
            pacc += psum;
        }
    }
    atomicAdd(&spair[lane], pacc);
    __syncthreads();

    // ---- m_v = We2v @ rowsum  (reuse sp) ----
    #pragma unroll
    for (int it = 0; it < 4; it++) {
        int h = w + it * 8;
        int i = lane;
        float a0 = 0.f, a1 = 0.f;
        #pragma unroll
        for (int c = 0; c < 32; c += 2) {
            a0 = fmaf(We2v[h * 32 + c + 0], srs[i * 33 + c + 0], a0);
            a1 = fmaf(We2v[h * 32 + c + 1], srs[i * 33 + c + 1], a1);
        }
        sp[i * 33 + h] = a0 + a1;
    }
    __syncthreads();

    // ---- a1 = silu(Wn1 @ [h_v, m_v] + bn1)  (reuse sq) ----
    #pragma unroll
    for (int it = 0; it < 4; it++) {
        int h = w + it * 8;
        int i = lane;
        float a = bn1[h];
        #pragma unroll
        for (int k = 0; k < 32; k++) a = fmaf(Wn1[h * 64 + k],      shv[i * 33 + k], a);
        #pragma unroll
        for (int k = 0; k < 32; k++) a = fmaf(Wn1[h * 64 + 32 + k], sp [i * 33 + k], a);
        sq[i * 34 + h] = silu_f(a);
    }
    __syncthreads();

    // ---- h_v_new = h_v + Wn2 @ a1 + bn2  (reuse ssj) ----
    #pragma unroll
    for (int it = 0; it < 4; it++) {
        int h = w + it * 8;
        int i = lane;
        float a = shv[i * 33 + h] + bn2[h];
        #pragma unroll
        for (int c = 0; c < 32; c++) a = fmaf(Wn2[h * 32 + c], sq[i * 34 + c], a);
        ssj[i * 34 + h] = a;
    }

    // ---- pairwise scalars ----
    float r2_l = 0.0f, s1_l = 0.0f, cusp_l = 0.0f;
    if (tid < 96) r2_l = sx[tid] * sx[tid];
    for (int idx = tid; idx < 496; idx += 256) {
        int rem = idx, pi = 0, cnt = 31;
        while (rem >= cnt) { rem -= cnt; pi++; cnt--; }
        int pj = pi + 1 + rem;
        float d0 = sx[pi * 3 + 0] - sx[pj * 3 + 0];
        float d1 = sx[pi * 3 + 1] - sx[pj * 3 + 1];
        float d2 = sx[pi * 3 + 2] - sx[pj * 3 + 2];
        float dd = fmaf(d0, d0, fmaf(d1, d1, d2 * d2));
        s1_l += log1pf((dd + 1e-8f) * 25.0f);
        float rc = sqrtf(dd + 1e-30f);
        bool same = (pi < 16) == (pj < 16);
        float gamma = same ? 0.25f : 0.5f;
        cusp_l += gamma * rc * __expf(-rc);
    }
    #pragma unroll
    for (int s = 16; s > 0; s >>= 1) {
        r2_l   += __shfl_xor_sync(0xffffffffu, r2_l,   s);
        s1_l   += __shfl_xor_sync(0xffffffffu, s1_l,   s);
        cusp_l += __shfl_xor_sync(0xffffffffu, cusp_l, s);
    }
    if (lane == 0) {
        atomicAdd(&sred[0], r2_l);
        atomicAdd(&sred[1], s1_l);
        atomicAdd(&sred[2], cusp_l);
    }
    __syncthreads();

    // ---- assemble f_in (130) ----
    if (tid < 32) {
        float hs = 0.0f;
        #pragma unroll
        for (int i2 = 0; i2 < 32; i2++) hs += ssj[i2 * 34 + tid];
        sfin[tid]      = hs;
        sfin[32 + tid] = hs * (1.0f / 32.0f);
        float ps = spair[tid];
        sfin[64 + tid] = ps;
        sfin[96 + tid] = ps * (1.0f / 496.0f);
    }
    if (tid == 0) {
        sfin[128] = sred[0] * (1.0f / 96.0f);
        sfin[129] = sred[1] * (1.0f / 496.0f);
        sfin[130] = 0.0f;  sfin[131] = 0.0f;
    }
    __syncthreads();

    // ---- readout: 130 -> 64 -> 64 -> 1 ----
    #pragma unroll 1
    for (int oo = 0; oo < 8; oo++) {
        int o = w * 8 + oo;
        float a = 0.0f;
        a = fmaf(Wf1[o * 130 + lane],      sfin[lane],      a);
        a = fmaf(Wf1[o * 130 + lane + 32], sfin[lane + 32], a);
        a = fmaf(Wf1[o * 130 + lane + 64], sfin[lane + 64], a);
        a = fmaf(Wf1[o * 130 + lane + 96], sfin[lane + 96], a);
        if (lane < 2) a = fmaf(Wf1[o * 130 + lane + 128], sfin[lane + 128], a);
        #pragma unroll
        for (int s = 16; s > 0; s >>= 1) a += __shfl_xor_sync(0xffffffffu, a, s);
        if (lane == 0) sf1[o] = silu_f(a + bf1[o]);
    }
    __syncthreads();

    #pragma unroll 1
    for (int oo = 0; oo < 8; oo++) {
        int o = w * 8 + oo;
        float a = fmaf(Wf2[o * 64 + lane],      sf1[lane],      0.0f);
        a       = fmaf(Wf2[o * 64 + lane + 32], sf1[lane + 32], a);
        #pragma unroll
        for (int s = 16; s > 0; s >>= 1) a += __shfl_xor_sync(0xffffffffu, a, s);
        if (lane == 0) sf2[o] = silu_f(a + bf2[o]);
    }
    __syncthreads();

    if (w == 0) {
        float a = fmaf(Wf3[lane],      sf2[lane],      0.0f);
        a       = fmaf(Wf3[lane + 32], sf2[lane + 32], a);
        #pragma unroll
        for (int s = 16; s > 0; s >>= 1) a += __shfl_xor_sync(0xffffffffu, a, s);
        if (lane == 0) out[b] = a + bf3[0] + sred[2];
    }
}

extern "C" void kernel_launch(void* const* d_in, const int* in_sizes, int n_in,
                              void* d_out, int out_size)
{
    const float* x      = (const float*)d_in[0];
    const float* W_node = (const float*)d_in[1];
    const float* b_node = (const float*)d_in[2];
    const float* We1    = (const float*)d_in[3];
    const float* be1    = (const float*)d_in[4];
    const float* We2    = (const float*)d_in[5];
    const float* be2    = (const float*)d_in[6];
    const float* Wv2e   = (const float*)d_in[7];
    const float* We2v   = (const float*)d_in[8];
    const float* Wu1    = (const float*)d_in[9];
    const float* bu1    = (const float*)d_in[10];
    const float* Wu2    = (const float*)d_in[11];
    const float* bu2    = (const float*)d_in[12];
    const float* Wn1    = (const float*)d_in[13];
    const float* bn1    = (const float*)d_in[14];
    const float* Wn2    = (const float*)d_in[15];
    const float* bn2    = (const float*)d_in[16];
    const float* Wf1    = (const float*)d_in[17];
    const float* bf1    = (const float*)d_in[18];
    const float* Wf2    = (const float*)d_in[19];
    const float* bf2    = (const float*)d_in[20];
    const float* Wf3    = (const float*)d_in[21];
    const float* bf3    = (const float*)d_in[22];

    const int dyn_smem = 8 * 2 * 32 * ST * (int)sizeof(float);   // 73728 B
    static bool attr_set = false;
    if (!attr_set) {
        cudaFuncSetAttribute(jastrow_kernel,
                             cudaFuncAttributeMaxDynamicSharedMemorySize, dyn_smem);
        attr_set = true;
    }

    int B = in_sizes[0] / 96;   // (B, 32, 3)
    jastrow_kernel<<<B, 256, dyn_smem>>>(x, W_node, b_node, We1, be1, We2, be2,
                                         Wv2e, We2v, Wu1, bu1, Wu2, bu2,
                                         Wn1, bn1, Wn2, bn2,
                                         Wf1, bf1, Wf2, bf2, Wf3, bf3,
                                         (float*)d_out);
}

// round 12
// speedup vs baseline: 1.8379x; 1.2570x over previous
#include <cuda_runtime.h>
#include <cuda_bf16.h>
#include <cstdint>

// CTNNBackflowStyleJastrow: B=1024, N=32, D=3, H=M=32, RH=64
// One CTA (256 threads = 8 warps) per batch element, 2 CTAs/SM.
// Edge loop: bf16 m16n8k16 mma (K=16 -> half the MMAs, half the smem bytes
// of the tf32 version). Activations stored as packed bf16x2, row stride 20
// words (conflict-free A-frag loads and stores). Weight fragment tables in
// shared memory, hoisted into registers per stage.

__device__ __forceinline__ float silu_f(float x) {
    return __fdividef(x, 1.0f + __expf(-x));
}
__device__ __forceinline__ uint32_t pk_bf2(float lo, float hi) {
    uint32_t r;
    asm("cvt.rn.bf16x2.f32 %0, %1, %2;" : "=r"(r) : "f"(hi), "f"(lo));
    return r;
}
__device__ __forceinline__ float bf_lo(uint32_t w) { return __uint_as_float(w << 16); }
__device__ __forceinline__ float bf_hi(uint32_t w) { return __uint_as_float(w & 0xffff0000u); }

__device__ __forceinline__ void mma_bf16(float& d0, float& d1, float& d2, float& d3,
                                         uint32_t a0, uint32_t a1, uint32_t a2, uint32_t a3,
                                         uint32_t b0, uint32_t b1) {
    asm volatile("mma.sync.aligned.m16n8k16.row.col.f32.bf16.bf16.f32 "
                 "{%0,%1,%2,%3}, {%4,%5,%6,%7}, {%8,%9}, {%0,%1,%2,%3};"
                 : "+f"(d0), "+f"(d1), "+f"(d2), "+f"(d3)
                 : "r"(a0), "r"(a1), "r"(a2), "r"(a3), "r"(b0), "r"(b1));
}

#define SH 20   // row stride in 32-bit words (16 data words + 4 pad; conflict-free)

__global__ __launch_bounds__(256, 2)
void jastrow_kernel(const float* __restrict__ x,
                    const float* __restrict__ W_node, const float* __restrict__ b_node,
                    const float* __restrict__ We1,  const float* __restrict__ be1,
                    const float* __restrict__ We2,  const float* __restrict__ be2,
                    const float* __restrict__ Wv2e, const float* __restrict__ We2v,
                    const float* __restrict__ Wu1,  const float* __restrict__ bu1,
                    const float* __restrict__ Wu2,  const float* __restrict__ bu2,
                    const float* __restrict__ Wn1,  const float* __restrict__ bn1,
                    const float* __restrict__ Wn2,  const float* __restrict__ bn2,
                    const float* __restrict__ Wf1,  const float* __restrict__ bf1,
                    const float* __restrict__ Wf2,  const float* __restrict__ bf2,
                    const float* __restrict__ Wf3,  const float* __restrict__ bf3,
                    float* __restrict__ out)
{
    __shared__ float sx[96];
    __shared__ float shv[32 * 33];
    __shared__ float sp [32 * 33];
    __shared__ __align__(8) float sq [32 * 34];
    __shared__ __align__(8) float ssj[32 * 34];
    __shared__ float srs[32 * 33];
    __shared__ __align__(8) float sbe1[32], sbe2[32], sbu2[32];
    __shared__ float spair[32];
    __shared__ float sred[3];
    __shared__ float sfin[132], sf1[64], sf2[64];
    // bf16 weight B-fragment tables
    __shared__ uint32_t sFe1[4 * 32];          // stage1: [nt][lane] b0 (b1 = 0)
    __shared__ __align__(8) uint2 sFe2[8 * 32]; // [(nt*2+kt)][lane] {b0,b1}
    __shared__ __align__(8) uint2 sFu1[8 * 32];
    __shared__ __align__(8) uint2 sFu2[8 * 32];
    extern __shared__ __align__(16) float dynsmem[];   // per warp: Tb[32*SH] + HE[32*SH]

    const int tid  = threadIdx.x;
    const int lane = tid & 31;
    const int w    = tid >> 5;
    const int b    = blockIdx.x;
    const int gid  = lane >> 2;
    const int tig  = lane & 3;

    // ---- stage inputs, biases, fragment tables ----
    if (tid < 96) sx[tid] = x[b * 96 + tid];
    if (tid < 32) {
        spair[tid] = 0.0f;
        sbe1[tid] = be1[tid]; sbe2[tid] = be2[tid]; sbu2[tid] = bu2[tid];
    }
    if (tid < 3)  sred[tid] = 0.0f;
    for (int idx = tid; idx < 4 * 32; idx += 256) {
        int nt = idx >> 5, ln = idx & 31;
        int g = ln >> 2, t = ln & 3;
        int n = 8 * nt + g;
        float w0 = (2 * t     < 5) ? We1[n * 5 + 2 * t]     : 0.0f;
        float w1 = (2 * t + 1 < 5) ? We1[n * 5 + 2 * t + 1] : 0.0f;
        sFe1[idx] = pk_bf2(w0, w1);
    }
    for (int idx = tid; idx < 8 * 32; idx += 256) {
        int pair = idx >> 5, ln = idx & 31;
        int nt = pair >> 1, kt = pair & 1;
        int g = ln >> 2, t = ln & 3;
        int n = 8 * nt + g;
        int k = 16 * kt + 2 * t;
        sFe2[idx] = make_uint2(pk_bf2(We2[n * 32 + k],     We2[n * 32 + k + 1]),
                               pk_bf2(We2[n * 32 + k + 8], We2[n * 32 + k + 9]));
        sFu1[idx] = make_uint2(pk_bf2(Wu1[n * 96 + k],     Wu1[n * 96 + k + 1]),
                               pk_bf2(Wu1[n * 96 + k + 8], Wu1[n * 96 + k + 9]));
        sFu2[idx] = make_uint2(pk_bf2(Wu2[n * 32 + k],     Wu2[n * 32 + k + 1]),
                               pk_bf2(Wu2[n * 32 + k + 8], Wu2[n * 32 + k + 9]));
    }
    __syncthreads();

    // ---- node phases ----
    #pragma unroll
    for (int it = 0; it < 4; it++) {
        int ch = w + it * 8;
        int i  = lane;
        float sf = (i >= 16) ? 1.0f : 0.0f;
        float a = b_node[ch]
                + W_node[ch * 4 + 0] * sx[i * 3 + 0]
                + W_node[ch * 4 + 1] * sx[i * 3 + 1]
                + W_node[ch * 4 + 2] * sx[i * 3 + 2]
                + W_node[ch * 4 + 3] * sf;
        shv[i * 33 + ch] = a;
    }
    __syncthreads();

    // p = h_v @ Wv2e^T
    #pragma unroll
    for (int it = 0; it < 4; it++) {
        int m = w + it * 8;
        int i = lane;
        float a0 = 0.f, a1 = 0.f;
        #pragma unroll
        for (int h = 0; h < 32; h += 2) {
            a0 = fmaf(Wv2e[m * 32 + h + 0], shv[i * 33 + h + 0], a0);
            a1 = fmaf(Wv2e[m * 32 + h + 1], shv[i * 33 + h + 1], a1);
        }
        sp[i * 33 + m] = a0 + a1;
    }
    __syncthreads();

    // q_i, s_j
    #pragma unroll
    for (int it = 0; it < 4; it++) {
        int h = w + it * 8;
        int i = lane;
        float aq = bu1[h], as = 0.f;
        #pragma unroll
        for (int m = 0; m < 32; m++) {
            float pv = sp[i * 33 + m];
            aq = fmaf(Wu1[h * 96 + 32 + m], pv, aq);
            as = fmaf(Wu1[h * 96 + 64 + m], pv, as);
        }
        sq [i * 34 + h] = aq;
        ssj[i * 34 + h] = as;
    }
    __syncthreads();

    // ---- edge loop: warp w owns rows i = 4w..4w+3 ----
    float* Tb = dynsmem + w * (2 * 32 * SH);
    float* HE = Tb + 32 * SH;
    float* F  = HE;                    // stage-1 feature scratch aliases HE

    const float xj0 = sx[lane * 3 + 0], xj1 = sx[lane * 3 + 1], xj2 = sx[lane * 3 + 2];
    float pacc = 0.0f;
    const int wi_red = lane >> 1;      // reduction word index
    const bool hi_red = lane & 1;

    #pragma unroll 1
    for (int ii = 0; ii < 4; ii++) {
        const int i = w * 4 + ii;

        // features (lane = edge j): bf16 row [r0,r1,r2,|r|,r^2,0...]
        {
            float fr0 = sx[i * 3 + 0] - xj0;
            float fr1 = sx[i * 3 + 1] - xj1;
            float fr2 = sx[i * 3 + 2] - xj2;
            float rr2 = fmaf(fr0, fr0, fmaf(fr1, fr1, fr2 * fr2));
            float tpl = rr2 + 1e-12f;
            float rr1 = tpl * __frsqrt_rn(tpl);
            __syncwarp();   // prior iter's reduction reads of HE done
            uint4 v0 = make_uint4(pk_bf2(fr0, fr1), pk_bf2(fr2, rr1),
                                  pk_bf2(rr2, 0.0f), 0u);
            *reinterpret_cast<uint4*>(&F[lane * SH])     = v0;
            *reinterpret_cast<uint4*>(&F[lane * SH + 4]) = make_uint4(0u, 0u, 0u, 0u);
            __syncwarp();
        }

        // stage 1: T = silu(F @ We1^T + be1)   (K=16, 1 K-tile; b1 = 0)
        {
            uint32_t wv[4]; float2 bb[4];
            #pragma unroll
            for (int nt = 0; nt < 4; nt++) {
                wv[nt] = sFe1[nt * 32 + lane];
                bb[nt] = *reinterpret_cast<const float2*>(&sbe1[8 * nt + 2 * tig]);
            }
            #pragma unroll
            for (int mt = 0; mt < 2; mt++) {
                uint32_t A0 = __float_as_uint(F[(16 * mt + gid) * SH + tig]);
                uint32_t A1 = __float_as_uint(F[(16 * mt + gid + 8) * SH + tig]);
                #pragma unroll
                for (int nt = 0; nt < 4; nt++) {
                    float d0 = bb[nt].x, d1 = bb[nt].y, d2 = bb[nt].x, d3 = bb[nt].y;
                    mma_bf16(d0, d1, d2, d3, A0, A1, 0u, 0u, wv[nt], 0u);
                    int r0 = (16 * mt + gid) * SH + 4 * nt + tig;
                    *reinterpret_cast<uint32_t*>(&Tb[r0]) =
                        pk_bf2(silu_f(d0), silu_f(d1));
                    *reinterpret_cast<uint32_t*>(&Tb[r0 + 8 * SH]) =
                        pk_bf2(silu_f(d2), silu_f(d3));
                }
            }
        }
        __syncwarp();

        // stage 2: HE = T @ We2^T + be2
        {
            uint2 wv[8]; float2 bb[4];
            #pragma unroll
            for (int nt = 0; nt < 4; nt++)
                bb[nt] = *reinterpret_cast<const float2*>(&sbe2[8 * nt + 2 * tig]);
            #pragma unroll
            for (int p = 0; p < 8; p++) wv[p] = sFe2[p * 32 + lane];
            #pragma unroll
            for (int mt = 0; mt < 2; mt++) {
                uint32_t Ar[8];
                #pragma unroll
                for (int kt = 0; kt < 2; kt++) {
                    int base = (16 * mt + gid) * SH + 8 * kt + tig;
                    Ar[4 * kt + 0] = __float_as_uint(Tb[base]);
                    Ar[4 * kt + 1] = __float_as_uint(Tb[base + 8 * SH]);
                    Ar[4 * kt + 2] = __float_as_uint(Tb[base + 4]);
                    Ar[4 * kt + 3] = __float_as_uint(Tb[base + 8 * SH + 4]);
                }
                #pragma unroll
                for (int nt = 0; nt < 4; nt++) {
                    float d0 = bb[nt].x, d1 = bb[nt].y, d2 = bb[nt].x, d3 = bb[nt].y;
                    #pragma unroll
                    for (int kt = 0; kt < 2; kt++)
                        mma_bf16(d0, d1, d2, d3,
                                 Ar[4 * kt], Ar[4 * kt + 1], Ar[4 * kt + 2], Ar[4 * kt + 3],
                                 wv[nt * 2 + kt].x, wv[nt * 2 + kt].y);
                    int r0 = (16 * mt + gid) * SH + 4 * nt + tig;
                    *reinterpret_cast<uint32_t*>(&HE[r0])          = pk_bf2(d0, d1);
                    *reinterpret_cast<uint32_t*>(&HE[r0 + 8 * SH]) = pk_bf2(d2, d3);
                }
            }
        }
        __syncwarp();

        // stage 3: T = silu(HE @ Wu1a^T + q_i[col] + s_j[row][col])
        {
            uint2 wv[8]; float2 qv[4];
            #pragma unroll
            for (int nt = 0; nt < 4; nt++)
                qv[nt] = *reinterpret_cast<const float2*>(&sq[i * 34 + 8 * nt + 2 * tig]);
            #pragma unroll
            for (int p = 0; p < 8; p++) wv[p] = sFu1[p * 32 + lane];
            #pragma unroll
            for (int mt = 0; mt < 2; mt++) {
                uint32_t Ar[8];
                #pragma unroll
                for (int kt = 0; kt < 2; kt++) {
                    int base = (16 * mt + gid) * SH + 8 * kt + tig;
                    Ar[4 * kt + 0] = __float_as_uint(HE[base]);
                    Ar[4 * kt + 1] = __float_as_uint(HE[base + 8 * SH]);
                    Ar[4 * kt + 2] = __float_as_uint(HE[base + 4]);
                    Ar[4 * kt + 3] = __float_as_uint(HE[base + 8 * SH + 4]);
                }
                #pragma unroll
                for (int nt = 0; nt < 4; nt++) {
                    int col = 8 * nt + 2 * tig;
                    float2 s0 = *reinterpret_cast<const float2*>(&ssj[(16 * mt + gid) * 34 + col]);
                    float2 s1 = *reinterpret_cast<const float2*>(&ssj[(16 * mt + gid + 8) * 34 + col]);
                    float d0 = qv[nt].x + s0.x, d1 = qv[nt].y + s0.y;
                    float d2 = qv[nt].x + s1.x, d3 = qv[nt].y + s1.y;
                    #pragma unroll
                    for (int kt = 0; kt < 2; kt++)
                        mma_bf16(d0, d1, d2, d3,
                                 Ar[4 * kt], Ar[4 * kt + 1], Ar[4 * kt + 2], Ar[4 * kt + 3],
                                 wv[nt * 2 + kt].x, wv[nt * 2 + kt].y);
                    int r0 = (16 * mt + gid) * SH + 4 * nt + tig;
                    *reinterpret_cast<uint32_t*>(&Tb[r0]) =
                        pk_bf2(silu_f(d0), silu_f(d1));
                    *reinterpret_cast<uint32_t*>(&Tb[r0 + 8 * SH]) =
                        pk_bf2(silu_f(d2), silu_f(d3));
                }
            }
        }
        __syncwarp();

        // stage 4: T = T @ Wu2^T + bu2   (in-place; per-mt sync between loads and stores)
        {
            uint2 wv[8]; float2 bb[4];
            #pragma unroll
            for (int nt = 0; nt < 4; nt++)
                bb[nt] = *reinterpret_cast<const float2*>(&sbu2[8 * nt + 2 * tig]);
            #pragma unroll
            for (int p = 0; p < 8; p++) wv[p] = sFu2[p * 32 + lane];
            #pragma unroll
            for (int mt = 0; mt < 2; mt++) {
                uint32_t Ar[8];
                #pragma unroll
                for (int kt = 0; kt < 2; kt++) {
                    int base = (16 * mt + gid) * SH + 8 * kt + tig;
                    Ar[4 * kt + 0] = __float_as_uint(Tb[base]);
                    Ar[4 * kt + 1] = __float_as_uint(Tb[base + 8 * SH]);
                    Ar[4 * kt + 2] = __float_as_uint(Tb[base + 4]);
                    Ar[4 * kt + 3] = __float_as_uint(Tb[base + 8 * SH + 4]);
                }
                __syncwarp();
                #pragma unroll
                for (int nt = 0; nt < 4; nt++) {
                    float d0 = bb[nt].x, d1 = bb[nt].y, d2 = bb[nt].x, d3 = bb[nt].y;
                    #pragma unroll
                    for (int kt = 0; kt < 2; kt++)
                        mma_bf16(d0, d1, d2, d3,
                                 Ar[4 * kt], Ar[4 * kt + 1], Ar[4 * kt + 2], Ar[4 * kt + 3],
                                 wv[nt * 2 + kt].x, wv[nt * 2 + kt].y);
                    int r0 = (16 * mt + gid) * SH + 4 * nt + tig;
                    *reinterpret_cast<uint32_t*>(&Tb[r0])          = pk_bf2(d0, d1);
                    *reinterpret_cast<uint32_t*>(&Tb[r0 + 8 * SH]) = pk_bf2(d2, d3);
                }
            }
        }
        __syncwarp();

        // reduction: lane = channel c; extract bf16 halves
        {
            float rsum = 0.0f, psum = 0.0f;
            #pragma unroll
            for (int jj = 0; jj < 32; jj++) {
                uint32_t tw = __float_as_uint(Tb[jj * SH + wi_red]);
                uint32_t hw = __float_as_uint(HE[jj * SH + wi_red]);
                float hn = hi_red ? bf_hi(tw) : bf_lo(tw);
                float he = hi_red ? bf_hi(hw) : bf_lo(hw);
                rsum += hn;
                float mk = (jj > i) ? 1.0f : 0.0f;
                psum = fmaf(mk, hn + he, psum);
            }
            uint32_t sw = __float_as_uint(Tb[i * SH + wi_red]);
            rsum -= hi_red ? bf_hi(sw) : bf_lo(sw);
            srs[i * 33 + lane] = rsum;
            pacc += psum;
        }
    }
    atomicAdd(&spair[lane], pacc);
    __syncthreads();

    // ---- m_v = We2v @ rowsum  (reuse sp) ----
    #pragma unroll
    for (int it = 0; it < 4; it++) {
        int h = w + it * 8;
        int i = lane;
        float a0 = 0.f, a1 = 0.f;
        #pragma unroll
        for (int c = 0; c < 32; c += 2) {
            a0 = fmaf(We2v[h * 32 + c + 0], srs[i * 33 + c + 0], a0);
            a1 = fmaf(We2v[h * 32 + c + 1], srs[i * 33 + c + 1], a1);
        }
        sp[i * 33 + h] = a0 + a1;
    }
    __syncthreads();

    // ---- a1 = silu(Wn1 @ [h_v, m_v] + bn1)  (reuse sq) ----
    #pragma unroll
    for (int it = 0; it < 4; it++) {
        int h = w + it * 8;
        int i = lane;
        float a = bn1[h];
        #pragma unroll
        for (int k = 0; k < 32; k++) a = fmaf(Wn1[h * 64 + k],      shv[i * 33 + k], a);
        #pragma unroll
        for (int k = 0; k < 32; k++) a = fmaf(Wn1[h * 64 + 32 + k], sp [i * 33 + k], a);
        sq[i * 34 + h] = silu_f(a);
    }
    __syncthreads();

    // ---- h_v_new = h_v + Wn2 @ a1 + bn2  (reuse ssj) ----
    #pragma unroll
    for (int it = 0; it < 4; it++) {
        int h = w + it * 8;
        int i = lane;
        float a = shv[i * 33 + h] + bn2[h];
        #pragma unroll
        for (int c = 0; c < 32; c++) a = fmaf(Wn2[h * 32 + c], sq[i * 34 + c], a);
        ssj[i * 34 + h] = a;
    }

    // ---- pairwise scalars ----
    float r2_l = 0.0f, s1_l = 0.0f, cusp_l = 0.0f;
    if (tid < 96) r2_l = sx[tid] * sx[tid];
    for (int idx = tid; idx < 496; idx += 256) {
        int rem = idx, pi = 0, cnt = 31;
        while (rem >= cnt) { rem -= cnt; pi++; cnt--; }
        int pj = pi + 1 + rem;
        float d0 = sx[pi * 3 + 0] - sx[pj * 3 + 0];
        float d1 = sx[pi * 3 + 1] - sx[pj * 3 + 1];
        float d2 = sx[pi * 3 + 2] - sx[pj * 3 + 2];
        float dd = fmaf(d0, d0, fmaf(d1, d1, d2 * d2));
        s1_l += log1pf((dd + 1e-8f) * 25.0f);
        float rc = sqrtf(dd + 1e-30f);
        bool same = (pi < 16) == (pj < 16);
        float gamma = same ? 0.25f : 0.5f;
        cusp_l += gamma * rc * __expf(-rc);
    }
    #pragma unroll
    for (int s = 16; s > 0; s >>= 1) {
        r2_l   += __shfl_xor_sync(0xffffffffu, r2_l,   s);
        s1_l   += __shfl_xor_sync(0xffffffffu, s1_l,   s);
        cusp_l += __shfl_xor_sync(0xffffffffu, cusp_l, s);
    }
    if (lane == 0) {
        atomicAdd(&sred[0], r2_l);
        atomicAdd(&sred[1], s1_l);
        atomicAdd(&sred[2], cusp_l);
    }
    __syncthreads();

    // ---- assemble f_in (130) ----
    if (tid < 32) {
        float hs = 0.0f;
        #pragma unroll
        for (int i2 = 0; i2 < 32; i2++) hs += ssj[i2 * 34 + tid];
        sfin[tid]      = hs;
        sfin[32 + tid] = hs * (1.0f / 32.0f);
        float ps = spair[tid];
        sfin[64 + tid] = ps;
        sfin[96 + tid] = ps * (1.0f / 496.0f);
    }
    if (tid == 0) {
        sfin[128] = sred[0] * (1.0f / 96.0f);
        sfin[129] = sred[1] * (1.0f / 496.0f);
        sfin[130] = 0.0f;  sfin[131] = 0.0f;
    }
    __syncthreads();

    // ---- readout: 130 -> 64 -> 64 -> 1 ----
    #pragma unroll 1
    for (int oo = 0; oo < 8; oo++) {
        int o = w * 8 + oo;
        float a = 0.0f;
        a = fmaf(Wf1[o * 130 + lane],      sfin[lane],      a);
        a = fmaf(Wf1[o * 130 + lane + 32], sfin[lane + 32], a);
        a = fmaf(Wf1[o * 130 + lane + 64], sfin[lane + 64], a);
        a = fmaf(Wf1[o * 130 + lane + 96], sfin[lane + 96], a);
        if (lane < 2) a = fmaf(Wf1[o * 130 + lane + 128], sfin[lane + 128], a);
        #pragma unroll
        for (int s = 16; s > 0; s >>= 1) a += __shfl_xor_sync(0xffffffffu, a, s);
        if (lane == 0) sf1[o] = silu_f(a + bf1[o]);
    }
    __syncthreads();

    #pragma unroll 1
    for (int oo = 0; oo < 8; oo++) {
        int o = w * 8 + oo;
        float a = fmaf(Wf2[o * 64 + lane],      sf1[lane],      0.0f);
        a       = fmaf(Wf2[o * 64 + lane + 32], sf1[lane + 32], a);
        #pragma unroll
        for (int s = 16; s > 0; s >>= 1) a += __shfl_xor_sync(0xffffffffu, a, s);
        if (lane == 0) sf2[o] = silu_f(a + bf2[o]);
    }
    __syncthreads();

    if (w == 0) {
        float a = fmaf(Wf3[lane],      sf2[lane],      0.0f);
        a       = fmaf(Wf3[lane + 32], sf2[lane + 32], a);
        #pragma unroll
        for (int s = 16; s > 0; s >>= 1) a += __shfl_xor_sync(0xffffffffu, a, s);
        if (lane == 0) out[b] = a + bf3[0] + sred[2];
    }
}

extern "C" void kernel_launch(void* const* d_in, const int* in_sizes, int n_in,
                              void* d_out, int out_size)
{
    const float* x      = (const float*)d_in[0];
    const float* W_node = (const float*)d_in[1];
    const float* b_node = (const float*)d_in[2];
    const float* We1    = (const float*)d_in[3];
    const float* be1    = (const float*)d_in[4];
    const float* We2    = (const float*)d_in[5];
    const float* be2    = (const float*)d_in[6];
    const float* Wv2e   = (const float*)d_in[7];
    const float* We2v   = (const float*)d_in[8];
    const float* Wu1    = (const float*)d_in[9];
    const float* bu1    = (const float*)d_in[10];
    const float* Wu2    = (const float*)d_in[11];
    const float* bu2    = (const float*)d_in[12];
    const float* Wn1    = (const float*)d_in[13];
    const float* bn1    = (const float*)d_in[14];
    const float* Wn2    = (const float*)d_in[15];
    const float* bn2    = (const float*)d_in[16];
    const float* Wf1    = (const float*)d_in[17];
    const float* bf1    = (const float*)d_in[18];
    const float* Wf2    = (const float*)d_in[19];
    const float* bf2    = (const float*)d_in[20];
    const float* Wf3    = (const float*)d_in[21];
    const float* bf3    = (const float*)d_in[22];

    const int dyn_smem = 8 * 2 * 32 * SH * (int)sizeof(float);   // 40960 B
    static bool attr_set = false;
    if (!attr_set) {
        cudaFuncSetAttribute(jastrow_kernel,
                             cudaFuncAttributeMaxDynamicSharedMemorySize, dyn_smem);
        attr_set = true;
    }

    int B = in_sizes[0] / 96;   // (B, 32, 3)
    jastrow_kernel<<<B, 256, dyn_smem>>>(x, W_node, b_node, We1, be1, We2, be2,
                                         Wv2e, We2v, Wu1, bu1, Wu2, bu2,
                                         Wn1, bn1, Wn2, bn2,
                                         Wf1, bf1, Wf2, bf2, Wf3, bf3,
                                         (float*)d_out);
}

// round 14
// speedup vs baseline: 1.9027x; 1.0353x over previous
#include <cuda_runtime.h>
#include <cuda_bf16.h>
#include <cstdint>

// CTNNBackflowStyleJastrow: B=1024, N=32, D=3, H=M=32, RH=64
// One CTA (256 threads = 8 warps) per batch element, 2 CTAs/SM.
// Edge loop: bf16 m16n8k16 mma; row/pair reductions taken IN REGISTERS from
// the mma C-fragments (masked adds + gid-axis shfl butterfly). Stage 4 has no
// stores; no smem readback loop.

__device__ __forceinline__ float silu_f(float x) {
    return __fdividef(x, 1.0f + __expf(-x));
}
__device__ __forceinline__ uint32_t pk_bf2(float lo, float hi) {
    uint32_t r;
    asm("cvt.rn.bf16x2.f32 %0, %1, %2;" : "=r"(r) : "f"(hi), "f"(lo));
    return r;
}
__device__ __forceinline__ void mma_bf16(float& d0, float& d1, float& d2, float& d3,
                                         uint32_t a0, uint32_t a1, uint32_t a2, uint32_t a3,
                                         uint32_t b0, uint32_t b1) {
    asm volatile("mma.sync.aligned.m16n8k16.row.col.f32.bf16.bf16.f32 "
                 "{%0,%1,%2,%3}, {%4,%5,%6,%7}, {%8,%9}, {%0,%1,%2,%3};"
                 : "+f"(d0), "+f"(d1), "+f"(d2), "+f"(d3)
                 : "r"(a0), "r"(a1), "r"(a2), "r"(a3), "r"(b0), "r"(b1));
}

#define SH 20   // row stride in 32-bit words (16 data + 4 pad; conflict-free)

__global__ __launch_bounds__(256, 2)
void jastrow_kernel(const float* __restrict__ x,
                    const float* __restrict__ W_node, const float* __restrict__ b_node,
                    const float* __restrict__ We1,  const float* __restrict__ be1,
                    const float* __restrict__ We2,  const float* __restrict__ be2,
                    const float* __restrict__ Wv2e, const float* __restrict__ We2v,
                    const float* __restrict__ Wu1,  const float* __restrict__ bu1,
                    const float* __restrict__ Wu2,  const float* __restrict__ bu2,
                    const float* __restrict__ Wn1,  const float* __restrict__ bn1,
                    const float* __restrict__ Wn2,  const float* __restrict__ bn2,
                    const float* __restrict__ Wf1,  const float* __restrict__ bf1,
                    const float* __restrict__ Wf2,  const float* __restrict__ bf2,
                    const float* __restrict__ Wf3,  const float* __restrict__ bf3,
                    float* __restrict__ out)
{
    __shared__ float sx[96];
    __shared__ float shv[32 * 33];
    __shared__ float sp [32 * 33];
    __shared__ __align__(8) float sq [32 * 34];
    __shared__ __align__(8) float ssj[32 * 34];
    __shared__ float srs[32 * 33];
    __shared__ __align__(8) float sbe1[32], sbe2[32], sbu2[32];
    __shared__ float spair[32];
    __shared__ float sred[3];
    __shared__ float sfin[132], sf1[64], sf2[64];
    __shared__ uint32_t sFe1[4 * 32];
    __shared__ __align__(8) uint2 sFe2[8 * 32];
    __shared__ __align__(8) uint2 sFu1[8 * 32];
    __shared__ __align__(8) uint2 sFu2[8 * 32];
    extern __shared__ __align__(16) float dynsmem[];   // per warp: Tb[32*SH] + HE[32*SH]

    const int tid  = threadIdx.x;
    const int lane = tid & 31;
    const int w    = tid >> 5;
    const int b    = blockIdx.x;
    const int gid  = lane >> 2;
    const int tig  = lane & 3;

    // ---- stage inputs, biases, fragment tables ----
    if (tid < 96) sx[tid] = x[b * 96 + tid];
    if (tid < 32) {
        spair[tid] = 0.0f;
        sbe1[tid] = be1[tid]; sbe2[tid] = be2[tid]; sbu2[tid] = bu2[tid];
    }
    if (tid < 3)  sred[tid] = 0.0f;
    for (int idx = tid; idx < 4 * 32; idx += 256) {
        int nt = idx >> 5, ln = idx & 31;
        int g = ln >> 2, t = ln & 3;
        int n = 8 * nt + g;
        float w0 = (2 * t     < 5) ? We1[n * 5 + 2 * t]     : 0.0f;
        float w1 = (2 * t + 1 < 5) ? We1[n * 5 + 2 * t + 1] : 0.0f;
        sFe1[idx] = pk_bf2(w0, w1);
    }
    for (int idx = tid; idx < 8 * 32; idx += 256) {
        int pair = idx >> 5, ln = idx & 31;
        int nt = pair >> 1, kt = pair & 1;
        int g = ln >> 2, t = ln & 3;
        int n = 8 * nt + g;
        int k = 16 * kt + 2 * t;
        sFe2[idx] = make_uint2(pk_bf2(We2[n * 32 + k],     We2[n * 32 + k + 1]),
                               pk_bf2(We2[n * 32 + k + 8], We2[n * 32 + k + 9]));
        sFu1[idx] = make_uint2(pk_bf2(Wu1[n * 96 + k],     Wu1[n * 96 + k + 1]),
                               pk_bf2(Wu1[n * 96 + k + 8], Wu1[n * 96 + k + 9]));
        sFu2[idx] = make_uint2(pk_bf2(Wu2[n * 32 + k],     Wu2[n * 32 + k + 1]),
                               pk_bf2(Wu2[n * 32 + k + 8], Wu2[n * 32 + k + 9]));
    }
    __syncthreads();

    // ---- node phases ----
    #pragma unroll
    for (int it = 0; it < 4; it++) {
        int ch = w + it * 8;
        int i  = lane;
        float sf = (i >= 16) ? 1.0f : 0.0f;
        float a = b_node[ch]
                + W_node[ch * 4 + 0] * sx[i * 3 + 0]
                + W_node[ch * 4 + 1] * sx[i * 3 + 1]
                + W_node[ch * 4 + 2] * sx[i * 3 + 2]
                + W_node[ch * 4 + 3] * sf;
        shv[i * 33 + ch] = a;
    }
    __syncthreads();

    // p = h_v @ Wv2e^T
    #pragma unroll
    for (int it = 0; it < 4; it++) {
        int m = w + it * 8;
        int i = lane;
        float a0 = 0.f, a1 = 0.f;
        #pragma unroll
        for (int h = 0; h < 32; h += 2) {
            a0 = fmaf(Wv2e[m * 32 + h + 0], shv[i * 33 + h + 0], a0);
            a1 = fmaf(Wv2e[m * 32 + h + 1], shv[i * 33 + h + 1], a1);
        }
        sp[i * 33 + m] = a0 + a1;
    }
    __syncthreads();

    // q_i, s_j
    #pragma unroll
    for (int it = 0; it < 4; it++) {
        int h = w + it * 8;
        int i = lane;
        float aq = bu1[h], as = 0.f;
        #pragma unroll
        for (int m = 0; m < 32; m++) {
            float pv = sp[i * 33 + m];
            aq = fmaf(Wu1[h * 96 + 32 + m], pv, aq);
            as = fmaf(Wu1[h * 96 + 64 + m], pv, as);
        }
        sq [i * 34 + h] = aq;
        ssj[i * 34 + h] = as;
    }
    __syncthreads();

    // ---- edge loop: warp w owns rows i = 4w..4w+3 ----
    float* Tb = dynsmem + w * (2 * 32 * SH);
    float* HE = Tb + 32 * SH;
    float* F  = HE;                    // stage-1 feature scratch aliases HE

    const float xj0 = sx[lane * 3 + 0], xj1 = sx[lane * 3 + 1], xj2 = sx[lane * 3 + 2];
    float ps[8];
    #pragma unroll
    for (int v = 0; v < 8; v++) ps[v] = 0.0f;

    #pragma unroll 1
    for (int ii = 0; ii < 4; ii++) {
        const int i = w * 4 + ii;

        // features (lane = edge j)
        {
            float fr0 = sx[i * 3 + 0] - xj0;
            float fr1 = sx[i * 3 + 1] - xj1;
            float fr2 = sx[i * 3 + 2] - xj2;
            float rr2 = fmaf(fr0, fr0, fmaf(fr1, fr1, fr2 * fr2));
            float tpl = rr2 + 1e-12f;
            float rr1 = tpl * __frsqrt_rn(tpl);
            __syncwarp();   // prior iter's stage-3 HE reads done
            uint4 v0 = make_uint4(pk_bf2(fr0, fr1), pk_bf2(fr2, rr1),
                                  pk_bf2(rr2, 0.0f), 0u);
            *reinterpret_cast<uint4*>(&F[lane * SH])     = v0;
            *reinterpret_cast<uint4*>(&F[lane * SH + 4]) = make_uint4(0u, 0u, 0u, 0u);
            __syncwarp();
        }

        // stage 1: T = silu(F @ We1^T + be1)
        {
            uint32_t wv[4]; float2 bb[4];
            #pragma unroll
            for (int nt = 0; nt < 4; nt++) {
                wv[nt] = sFe1[nt * 32 + lane];
                bb[nt] = *reinterpret_cast<const float2*>(&sbe1[8 * nt + 2 * tig]);
            }
            #pragma unroll
            for (int mt = 0; mt < 2; mt++) {
                uint32_t A0 = __float_as_uint(F[(16 * mt + gid) * SH + tig]);
                uint32_t A1 = __float_as_uint(F[(16 * mt + gid + 8) * SH + tig]);
                #pragma unroll
                for (int nt = 0; nt < 4; nt++) {
                    float d0 = bb[nt].x, d1 = bb[nt].y, d2 = bb[nt].x, d3 = bb[nt].y;
                    mma_bf16(d0, d1, d2, d3, A0, A1, 0u, 0u, wv[nt], 0u);
                    int r0 = (16 * mt + gid) * SH + 4 * nt + tig;
                    *reinterpret_cast<uint32_t*>(&Tb[r0]) =
                        pk_bf2(silu_f(d0), silu_f(d1));
                    *reinterpret_cast<uint32_t*>(&Tb[r0 + 8 * SH]) =
                        pk_bf2(silu_f(d2), silu_f(d3));
                }
            }
        }
        __syncwarp();

        // stage 2: HE = T @ We2^T + be2 ; masked he (j>i) -> ps in regs
        {
            uint2 wv[8]; float2 bb[4];
            #pragma unroll
            for (int nt = 0; nt < 4; nt++)
                bb[nt] = *reinterpret_cast<const float2*>(&sbe2[8 * nt + 2 * tig]);
            #pragma unroll
            for (int p = 0; p < 8; p++) wv[p] = sFe2[p * 32 + lane];
            #pragma unroll
            for (int mt = 0; mt < 2; mt++) {
                uint32_t Ar[8];
                #pragma unroll
                for (int kt = 0; kt < 2; kt++) {
                    int base = (16 * mt + gid) * SH + 8 * kt + tig;
                    Ar[4 * kt + 0] = __float_as_uint(Tb[base]);
                    Ar[4 * kt + 1] = __float_as_uint(Tb[base + 8 * SH]);
                    Ar[4 * kt + 2] = __float_as_uint(Tb[base + 4]);
                    Ar[4 * kt + 3] = __float_as_uint(Tb[base + 8 * SH + 4]);
                }
                const int j0 = 16 * mt + gid, j1 = j0 + 8;
                const bool plo = (j0 > i), phi = (j1 > i);
                #pragma unroll
                for (int nt = 0; nt < 4; nt++) {
                    float d0 = bb[nt].x, d1 = bb[nt].y, d2 = bb[nt].x, d3 = bb[nt].y;
                    #pragma unroll
                    for (int kt = 0; kt < 2; kt++)
                        mma_bf16(d0, d1, d2, d3,
                                 Ar[4 * kt], Ar[4 * kt + 1], Ar[4 * kt + 2], Ar[4 * kt + 3],
                                 wv[nt * 2 + kt].x, wv[nt * 2 + kt].y);
                    int r0 = (16 * mt + gid) * SH + 4 * nt + tig;
                    *reinterpret_cast<uint32_t*>(&HE[r0])          = pk_bf2(d0, d1);
                    *reinterpret_cast<uint32_t*>(&HE[r0 + 8 * SH]) = pk_bf2(d2, d3);
                    if (plo) { ps[nt * 2] += d0; ps[nt * 2 + 1] += d1; }
                    if (phi) { ps[nt * 2] += d2; ps[nt * 2 + 1] += d3; }
                }
            }
        }
        __syncwarp();

        // stage 3: T = silu(HE @ Wu1a^T + q_i[col] + s_j[row][col])
        {
            uint2 wv[8]; float2 qv[4];
            #pragma unroll
            for (int nt = 0; nt < 4; nt++)
                qv[nt] = *reinterpret_cast<const float2*>(&sq[i * 34 + 8 * nt + 2 * tig]);
            #pragma unroll
            for (int p = 0; p < 8; p++) wv[p] = sFu1[p * 32 + lane];
            #pragma unroll
            for (int mt = 0; mt < 2; mt++) {
                uint32_t Ar[8];
                #pragma unroll
                for (int kt = 0; kt < 2; kt++) {
                    int base = (16 * mt + gid) * SH + 8 * kt + tig;
                    Ar[4 * kt + 0] = __float_as_uint(HE[base]);
                    Ar[4 * kt + 1] = __float_as_uint(HE[base + 8 * SH]);
                    Ar[4 * kt + 2] = __float_as_uint(HE[base + 4]);
                    Ar[4 * kt + 3] = __float_as_uint(HE[base + 8 * SH + 4]);
                }
                #pragma unroll
                for (int nt = 0; nt < 4; nt++) {
                    int col = 8 * nt + 2 * tig;
                    float2 s0 = *reinterpret_cast<const float2*>(&ssj[(16 * mt + gid) * 34 + col]);
                    float2 s1 = *reinterpret_cast<const float2*>(&ssj[(16 * mt + gid + 8) * 34 + col]);
                    float d0 = qv[nt].x + s0.x, d1 = qv[nt].y + s0.y;
                    float d2 = qv[nt].x + s1.x, d3 = qv[nt].y + s1.y;
                    #pragma unroll
                    for (int kt = 0; kt < 2; kt++)
                        mma_bf16(d0, d1, d2, d3,
                                 Ar[4 * kt], Ar[4 * kt + 1], Ar[4 * kt + 2], Ar[4 * kt + 3],
                                 wv[nt * 2 + kt].x, wv[nt * 2 + kt].y);
                    int r0 = (16 * mt + gid) * SH + 4 * nt + tig;
                    *reinterpret_cast<uint32_t*>(&Tb[r0]) =
                        pk_bf2(silu_f(d0), silu_f(d1));
                    *reinterpret_cast<uint32_t*>(&Tb[r0 + 8 * SH]) =
                        pk_bf2(silu_f(d2), silu_f(d3));
                }
            }
        }
        __syncwarp();

        // stage 4: hn = T @ Wu2^T + bu2 -- NO stores; masked adds into rs/ps
        {
            uint2 wv[8]; float2 bb[4];
            float rs[8];
            #pragma unroll
            for (int v = 0; v < 8; v++) rs[v] = 0.0f;
            #pragma unroll
            for (int nt = 0; nt < 4; nt++)
                bb[nt] = *reinterpret_cast<const float2*>(&sbu2[8 * nt + 2 * tig]);
            #pragma unroll
            for (int p = 0; p < 8; p++) wv[p] = sFu2[p * 32 + lane];
            #pragma unroll
            for (int mt = 0; mt < 2; mt++) {
                uint32_t Ar[8];
                #pragma unroll
                for (int kt = 0; kt < 2; kt++) {
                    int base = (16 * mt + gid) * SH + 8 * kt + tig;
                    Ar[4 * kt + 0] = __float_as_uint(Tb[base]);
                    Ar[4 * kt + 1] = __float_as_uint(Tb[base + 8 * SH]);
                    Ar[4 * kt + 2] = __float_as_uint(Tb[base + 4]);
                    Ar[4 * kt + 3] = __float_as_uint(Tb[base + 8 * SH + 4]);
                }
                const int j0 = 16 * mt + gid, j1 = j0 + 8;
                const bool plo = (j0 > i),  phi = (j1 > i);
                const bool nlo = (j0 != i), nhi = (j1 != i);
                #pragma unroll
                for (int nt = 0; nt < 4; nt++) {
                    float d0 = bb[nt].x, d1 = bb[nt].y, d2 = bb[nt].x, d3 = bb[nt].y;
                    #pragma unroll
                    for (int kt = 0; kt < 2; kt++)
                        mma_bf16(d0, d1, d2, d3,
                                 Ar[4 * kt], Ar[4 * kt + 1], Ar[4 * kt + 2], Ar[4 * kt + 3],
                                 wv[nt * 2 + kt].x, wv[nt * 2 + kt].y);
                    if (nlo) { rs[nt * 2] += d0; rs[nt * 2 + 1] += d1; }
                    if (nhi) { rs[nt * 2] += d2; rs[nt * 2 + 1] += d3; }
                    if (plo) { ps[nt * 2] += d0; ps[nt * 2 + 1] += d1; }
                    if (phi) { ps[nt * 2] += d2; ps[nt * 2 + 1] += d3; }
                }
            }
            // butterfly over gid axis; gid==0 lanes hold full row sums
            #pragma unroll
            for (int v = 0; v < 8; v++) {
                rs[v] += __shfl_xor_sync(0xffffffffu, rs[v], 4);
                rs[v] += __shfl_xor_sync(0xffffffffu, rs[v], 8);
                rs[v] += __shfl_xor_sync(0xffffffffu, rs[v], 16);
            }
            if (gid == 0) {
                #pragma unroll
                for (int nt = 0; nt < 4; nt++) {
                    srs[i * 33 + 8 * nt + 2 * tig]     = rs[nt * 2];
                    srs[i * 33 + 8 * nt + 2 * tig + 1] = rs[nt * 2 + 1];
                }
            }
        }
    }

    // pair-sum: butterfly then one atomic set per warp
    #pragma unroll
    for (int v = 0; v < 8; v++) {
        ps[v] += __shfl_xor_sync(0xffffffffu, ps[v], 4);
        ps[v] += __shfl_xor_sync(0xffffffffu, ps[v], 8);
        ps[v] += __shfl_xor_sync(0xffffffffu, ps[v], 16);
    }
    if (gid == 0) {
        #pragma unroll
        for (int nt = 0; nt < 4; nt++) {
            atomicAdd(&spair[8 * nt + 2 * tig],     ps[nt * 2]);
            atomicAdd(&spair[8 * nt + 2 * tig + 1], ps[nt * 2 + 1]);
        }
    }
    __syncthreads();

    // ---- m_v = We2v @ rowsum  (reuse sp) ----
    #pragma unroll
    for (int it = 0; it < 4; it++) {
        int h = w + it * 8;
        int i = lane;
        float a0 = 0.f, a1 = 0.f;
        #pragma unroll
        for (int c = 0; c < 32; c += 2) {
            a0 = fmaf(We2v[h * 32 + c + 0], srs[i * 33 + c + 0], a0);
            a1 = fmaf(We2v[h * 32 + c + 1], srs[i * 33 + c + 1], a1);
        }
        sp[i * 33 + h] = a0 + a1;
    }
    __syncthreads();

    // ---- a1 = silu(Wn1 @ [h_v, m_v] + bn1)  (reuse sq) ----
    #pragma unroll
    for (int it = 0; it < 4; it++) {
        int h = w + it * 8;
        int i = lane;
        float a = bn1[h];
        #pragma unroll
        for (int k = 0; k < 32; k++) a = fmaf(Wn1[h * 64 + k],      shv[i * 33 + k], a);
        #pragma unroll
        for (int k = 0; k < 32; k++) a = fmaf(Wn1[h * 64 + 32 + k], sp [i * 33 + k], a);
        sq[i * 34 + h] = silu_f(a);
    }
    __syncthreads();

    // ---- h_v_new = h_v + Wn2 @ a1 + bn2  (reuse ssj) ----
    #pragma unroll
    for (int it = 0; it < 4; it++) {
        int h = w + it * 8;
        int i = lane;
        float a = shv[i * 33 + h] + bn2[h];
        #pragma unroll
        for (int c = 0; c < 32; c++) a = fmaf(Wn2[h * 32 + c], sq[i * 34 + c], a);
        ssj[i * 34 + h] = a;
    }

    // ---- pairwise scalars ----
    float r2_l = 0.0f, s1_l = 0.0f, cusp_l = 0.0f;
    if (tid < 96) r2_l = sx[tid] * sx[tid];
    for (int idx = tid; idx < 496; idx += 256) {
        int rem = idx, pi = 0, cnt = 31;
        while (rem >= cnt) { rem -= cnt; pi++; cnt--; }
        int pj = pi + 1 + rem;
        float d0 = sx[pi * 3 + 0] - sx[pj * 3 + 0];
        float d1 = sx[pi * 3 + 1] - sx[pj * 3 + 1];
        float d2 = sx[pi * 3 + 2] - sx[pj * 3 + 2];
        float dd = fmaf(d0, d0, fmaf(d1, d1, d2 * d2));
        s1_l += log1pf((dd + 1e-8f) * 25.0f);
        float rc = sqrtf(dd + 1e-30f);
        bool same = (pi < 16) == (pj < 16);
        float gamma = same ? 0.25f : 0.5f;
        cusp_l += gamma * rc * __expf(-rc);
    }
    #pragma unroll
    for (int s = 16; s > 0; s >>= 1) {
        r2_l   += __shfl_xor_sync(0xffffffffu, r2_l,   s);
        s1_l   += __shfl_xor_sync(0xffffffffu, s1_l,   s);
        cusp_l += __shfl_xor_sync(0xffffffffu, cusp_l, s);
    }
    if (lane == 0) {
        atomicAdd(&sred[0], r2_l);
        atomicAdd(&sred[1], s1_l);
        atomicAdd(&sred[2], cusp_l);
    }
    __syncthreads();

    // ---- assemble f_in (130) ----
    if (tid < 32) {
        float hs = 0.0f;
        #pragma unroll
        for (int i2 = 0; i2 < 32; i2++) hs += ssj[i2 * 34 + tid];
        sfin[tid]      = hs;
        sfin[32 + tid] = hs * (1.0f / 32.0f);
        float p2 = spair[tid];
        sfin[64 + tid] = p2;
        sfin[96 + tid] = p2 * (1.0f / 496.0f);
    }
    if (tid == 0) {
        sfin[128] = sred[0] * (1.0f / 96.0f);
        sfin[129] = sred[1] * (1.0f / 496.0f);
        sfin[130] = 0.0f;  sfin[131] = 0.0f;
    }
    __syncthreads();

    // ---- readout: 130 -> 64 -> 64 -> 1 ----
    #pragma unroll 1
    for (int oo = 0; oo < 8; oo++) {
        int o = w * 8 + oo;
        float a = 0.0f;
        a = fmaf(Wf1[o * 130 + lane],      sfin[lane],      a);
        a = fmaf(Wf1[o * 130 + lane + 32], sfin[lane + 32], a);
        a = fmaf(Wf1[o * 130 + lane + 64], sfin[lane + 64], a);
        a = fmaf(Wf1[o * 130 + lane + 96], sfin[lane + 96], a);
        if (lane < 2) a = fmaf(Wf1[o * 130 + lane + 128], sfin[lane + 128], a);
        #pragma unroll
        for (int s = 16; s > 0; s >>= 1) a += __shfl_xor_sync(0xffffffffu, a, s);
        if (lane == 0) sf1[o] = silu_f(a + bf1[o]);
    }
    __syncthreads();

    #pragma unroll 1
    for (int oo = 0; oo < 8; oo++) {
        int o = w * 8 + oo;
        float a = fmaf(Wf2[o * 64 + lane],      sf1[lane],      0.0f);
        a       = fmaf(Wf2[o * 64 + lane + 32], sf1[lane + 32], a);
        #pragma unroll
        for (int s = 16; s > 0; s >>= 1) a += __shfl_xor_sync(0xffffffffu, a, s);
        if (lane == 0) sf2[o] = silu_f(a + bf2[o]);
    }
    __syncthreads();

    if (w == 0) {
        float a = fmaf(Wf3[lane],      sf2[lane],      0.0f);
        a       = fmaf(Wf3[lane + 32], sf2[lane + 32], a);
        #pragma unroll
        for (int s = 16; s > 0; s >>= 1) a += __shfl_xor_sync(0xffffffffu, a, s);
        if (lane == 0) out[b] = a + bf3[0] + sred[2];
    }
}

extern "C" void kernel_launch(void* const* d_in, const int* in_sizes, int n_in,
                              void* d_out, int out_size)
{
    const float* x      = (const float*)d_in[0];
    const float* W_node = (const float*)d_in[1];
    const float* b_node = (const float*)d_in[2];
    const float* We1    = (const float*)d_in[3];
    const float* be1    = (const float*)d_in[4];
    const float* We2    = (const float*)d_in[5];
    const float* be2    = (const float*)d_in[6];
    const float* Wv2e   = (const float*)d_in[7];
    const float* We2v   = (const float*)d_in[8];
    const float* Wu1    = (const float*)d_in[9];
    const float* bu1    = (const float*)d_in[10];
    const float* Wu2    = (const float*)d_in[11];
    const float* bu2    = (const float*)d_in[12];
    const float* Wn1    = (const float*)d_in[13];
    const float* bn1    = (const float*)d_in[14];
    const float* Wn2    = (const float*)d_in[15];
    const float* bn2    = (const float*)d_in[16];
    const float* Wf1    = (const float*)d_in[17];
    const float* bf1    = (const float*)d_in[18];
    const float* Wf2    = (const float*)d_in[19];
    const float* bf2    = (const float*)d_in[20];
    const float* Wf3    = (const float*)d_in[21];
    const float* bf3    = (const float*)d_in[22];

    const int dyn_smem = 8 * 2 * 32 * SH * (int)sizeof(float);   // 40960 B
    static bool attr_set = false;
    if (!attr_set) {
        cudaFuncSetAttribute(jastrow_kernel,
                             cudaFuncAttributeMaxDynamicSharedMemorySize, dyn_smem);
        attr_set = true;
    }

    int B = in_sizes[0] / 96;   // (B, 32, 3)
    jastrow_kernel<<<B, 256, dyn_smem>>>(x, W_node, b_node, We1, be1, We2, be2,
                                         Wv2e, We2v, Wu1, bu1, Wu2, bu2,
                                         Wn1, bn1, Wn2, bn2,
                                         Wf1, bf1, Wf2, bf2, Wf3, bf3,
                                         (float*)d_out);
}

// round 15
// speedup vs baseline: 1.9534x; 1.0266x over previous
#include <cuda_runtime.h>
#include <cuda_bf16.h>
#include <cstdint>

// CTNNBackflowStyleJastrow: B=1024, N=32, D=3, H=M=32, RH=64
// One CTA (256 threads = 8 warps) per batch element, 2 CTAs/SM.
// Edge loop: bf16 m16n8k16 mma, in-register masked reductions.
// Node phases: 4-wide vectorized (warp w owns channels 4w..4w+3; LDS.128
// activations at stride 36, uniform LDG.128 weights, STS.128 outputs).

__device__ __forceinline__ float silu_f(float x) {
    return __fdividef(x, 1.0f + __expf(-x));
}
__device__ __forceinline__ uint32_t pk_bf2(float lo, float hi) {
    uint32_t r;
    asm("cvt.rn.bf16x2.f32 %0, %1, %2;" : "=r"(r) : "f"(hi), "f"(lo));
    return r;
}
__device__ __forceinline__ void mma_bf16(float& d0, float& d1, float& d2, float& d3,
                                         uint32_t a0, uint32_t a1, uint32_t a2, uint32_t a3,
                                         uint32_t b0, uint32_t b1) {
    asm volatile("mma.sync.aligned.m16n8k16.row.col.f32.bf16.bf16.f32 "
                 "{%0,%1,%2,%3}, {%4,%5,%6,%7}, {%8,%9}, {%0,%1,%2,%3};"
                 : "+f"(d0), "+f"(d1), "+f"(d2), "+f"(d3)
                 : "r"(a0), "r"(a1), "r"(a2), "r"(a3), "r"(b0), "r"(b1));
}
__device__ __forceinline__ float dot4(float4 a, float4 b) {
    return fmaf(a.x, b.x, fmaf(a.y, b.y, fmaf(a.z, b.z, a.w * b.w)));
}

#define SH 20   // edge buffer row stride (words)
#define SN 36   // node array row stride (words): LDS.128 conflict-free, 16B aligned

__global__ __launch_bounds__(256, 2)
void jastrow_kernel(const float* __restrict__ x,
                    const float* __restrict__ W_node, const float* __restrict__ b_node,
                    const float* __restrict__ We1,  const float* __restrict__ be1,
                    const float* __restrict__ We2,  const float* __restrict__ be2,
                    const float* __restrict__ Wv2e, const float* __restrict__ We2v,
                    const float* __restrict__ Wu1,  const float* __restrict__ bu1,
                    const float* __restrict__ Wu2,  const float* __restrict__ bu2,
                    const float* __restrict__ Wn1,  const float* __restrict__ bn1,
                    const float* __restrict__ Wn2,  const float* __restrict__ bn2,
                    const float* __restrict__ Wf1,  const float* __restrict__ bf1,
                    const float* __restrict__ Wf2,  const float* __restrict__ bf2,
                    const float* __restrict__ Wf3,  const float* __restrict__ bf3,
                    float* __restrict__ out)
{
    __shared__ float sx[96];
    __shared__ __align__(16) float shv[32 * SN];   // h_v
    __shared__ __align__(16) float sp [32 * SN];   // p, later m_v
    __shared__ __align__(16) float sq [32 * SN];   // q_i, later a1
    __shared__ __align__(16) float ssj[32 * SN];   // s_j, later h_v_new
    __shared__ __align__(16) float srs[32 * SN];   // row sums
    __shared__ __align__(8) float sbe1[32], sbe2[32], sbu2[32];
    __shared__ float spair[32];
    __shared__ float sred[3];
    __shared__ float sfin[132], sf1[64], sf2[64];
    __shared__ uint32_t sFe1[4 * 32];
    __shared__ __align__(8) uint2 sFe2[8 * 32];
    __shared__ __align__(8) uint2 sFu1[8 * 32];
    __shared__ __align__(8) uint2 sFu2[8 * 32];
    extern __shared__ __align__(16) float dynsmem[];   // per warp: Tb[32*SH] + HE[32*SH]

    const int tid  = threadIdx.x;
    const int lane = tid & 31;
    const int w    = tid >> 5;
    const int b    = blockIdx.x;
    const int gid  = lane >> 2;
    const int tig  = lane & 3;
    const int ch0  = 4 * w;            // node-phase channel base for this warp

    // ---- stage inputs, biases, fragment tables ----
    if (tid < 96) sx[tid] = x[b * 96 + tid];
    if (tid < 32) {
        spair[tid] = 0.0f;
        sbe1[tid] = be1[tid]; sbe2[tid] = be2[tid]; sbu2[tid] = bu2[tid];
    }
    if (tid < 3)  sred[tid] = 0.0f;
    for (int idx = tid; idx < 4 * 32; idx += 256) {
        int nt = idx >> 5, ln = idx & 31;
        int g = ln >> 2, t = ln & 3;
        int n = 8 * nt + g;
        float w0 = (2 * t     < 5) ? We1[n * 5 + 2 * t]     : 0.0f;
        float w1 = (2 * t + 1 < 5) ? We1[n * 5 + 2 * t + 1] : 0.0f;
        sFe1[idx] = pk_bf2(w0, w1);
    }
    for (int idx = tid; idx < 8 * 32; idx += 256) {
        int pair = idx >> 5, ln = idx & 31;
        int nt = pair >> 1, kt = pair & 1;
        int g = ln >> 2, t = ln & 3;
        int n = 8 * nt + g;
        int k = 16 * kt + 2 * t;
        sFe2[idx] = make_uint2(pk_bf2(We2[n * 32 + k],     We2[n * 32 + k + 1]),
                               pk_bf2(We2[n * 32 + k + 8], We2[n * 32 + k + 9]));
        sFu1[idx] = make_uint2(pk_bf2(Wu1[n * 96 + k],     Wu1[n * 96 + k + 1]),
                               pk_bf2(Wu1[n * 96 + k + 8], Wu1[n * 96 + k + 9]));
        sFu2[idx] = make_uint2(pk_bf2(Wu2[n * 32 + k],     Wu2[n * 32 + k + 1]),
                               pk_bf2(Wu2[n * 32 + k + 8], Wu2[n * 32 + k + 9]));
    }
    __syncthreads();

    // ---- h_v: channels ch0..ch0+3 for node i = lane ----
    {
        int i = lane;
        float sf = (i >= 16) ? 1.0f : 0.0f;
        float4 xin = make_float4(sx[i * 3 + 0], sx[i * 3 + 1], sx[i * 3 + 2], sf);
        float4 acc;
        acc.x = b_node[ch0 + 0] + dot4(*reinterpret_cast<const float4*>(&W_node[(ch0 + 0) * 4]), xin);
        acc.y = b_node[ch0 + 1] + dot4(*reinterpret_cast<const float4*>(&W_node[(ch0 + 1) * 4]), xin);
        acc.z = b_node[ch0 + 2] + dot4(*reinterpret_cast<const float4*>(&W_node[(ch0 + 2) * 4]), xin);
        acc.w = b_node[ch0 + 3] + dot4(*reinterpret_cast<const float4*>(&W_node[(ch0 + 3) * 4]), xin);
        *reinterpret_cast<float4*>(&shv[i * SN + ch0]) = acc;
    }
    __syncthreads();

    // ---- p = h_v @ Wv2e^T ----
    {
        int i = lane;
        float4 acc = make_float4(0.f, 0.f, 0.f, 0.f);
        #pragma unroll
        for (int hq = 0; hq < 8; hq++) {
            float4 av = *reinterpret_cast<const float4*>(&shv[i * SN + 4 * hq]);
            acc.x = fmaf(1.0f, dot4(*reinterpret_cast<const float4*>(&Wv2e[(ch0 + 0) * 32 + 4 * hq]), av), acc.x);
            acc.y = fmaf(1.0f, dot4(*reinterpret_cast<const float4*>(&Wv2e[(ch0 + 1) * 32 + 4 * hq]), av), acc.y);
            acc.z = fmaf(1.0f, dot4(*reinterpret_cast<const float4*>(&Wv2e[(ch0 + 2) * 32 + 4 * hq]), av), acc.z);
            acc.w = fmaf(1.0f, dot4(*reinterpret_cast<const float4*>(&Wv2e[(ch0 + 3) * 32 + 4 * hq]), av), acc.w);
        }
        *reinterpret_cast<float4*>(&sp[i * SN + ch0]) = acc;
    }
    __syncthreads();

    // ---- q_i = Wu1[:,32:64]@p_i + bu1 ; s_j = Wu1[:,64:96]@p_j ----
    {
        int i = lane;
        float4 aq = make_float4(bu1[ch0], bu1[ch0 + 1], bu1[ch0 + 2], bu1[ch0 + 3]);
        float4 as = make_float4(0.f, 0.f, 0.f, 0.f);
        #pragma unroll
        for (int hq = 0; hq < 8; hq++) {
            float4 pv = *reinterpret_cast<const float4*>(&sp[i * SN + 4 * hq]);
            aq.x = fmaf(1.0f, dot4(*reinterpret_cast<const float4*>(&Wu1[(ch0 + 0) * 96 + 32 + 4 * hq]), pv), aq.x);
            aq.y = fmaf(1.0f, dot4(*reinterpret_cast<const float4*>(&Wu1[(ch0 + 1) * 96 + 32 + 4 * hq]), pv), aq.y);
            aq.z = fmaf(1.0f, dot4(*reinterpret_cast<const float4*>(&Wu1[(ch0 + 2) * 96 + 32 + 4 * hq]), pv), aq.z);
            aq.w = fmaf(1.0f, dot4(*reinterpret_cast<const float4*>(&Wu1[(ch0 + 3) * 96 + 32 + 4 * hq]), pv), aq.w);
            as.x = fmaf(1.0f, dot4(*reinterpret_cast<const float4*>(&Wu1[(ch0 + 0) * 96 + 64 + 4 * hq]), pv), as.x);
            as.y = fmaf(1.0f, dot4(*reinterpret_cast<const float4*>(&Wu1[(ch0 + 1) * 96 + 64 + 4 * hq]), pv), as.y);
            as.z = fmaf(1.0f, dot4(*reinterpret_cast<const float4*>(&Wu1[(ch0 + 2) * 96 + 64 + 4 * hq]), pv), as.z);
            as.w = fmaf(1.0f, dot4(*reinterpret_cast<const float4*>(&Wu1[(ch0 + 3) * 96 + 64 + 4 * hq]), pv), as.w);
        }
        *reinterpret_cast<float4*>(&sq [i * SN + ch0]) = aq;
        *reinterpret_cast<float4*>(&ssj[i * SN + ch0]) = as;
    }
    __syncthreads();

    // ---- edge loop: warp w owns rows i = 4w..4w+3 ----
    float* Tb = dynsmem + w * (2 * 32 * SH);
    float* HE = Tb + 32 * SH;
    float* F  = HE;                    // stage-1 feature scratch aliases HE

    const float xj0 = sx[lane * 3 + 0], xj1 = sx[lane * 3 + 1], xj2 = sx[lane * 3 + 2];
    float ps[8];
    #pragma unroll
    for (int v = 0; v < 8; v++) ps[v] = 0.0f;

    #pragma unroll 1
    for (int ii = 0; ii < 4; ii++) {
        const int i = w * 4 + ii;

        // features (lane = edge j)
        {
            float fr0 = sx[i * 3 + 0] - xj0;
            float fr1 = sx[i * 3 + 1] - xj1;
            float fr2 = sx[i * 3 + 2] - xj2;
            float rr2 = fmaf(fr0, fr0, fmaf(fr1, fr1, fr2 * fr2));
            float tpl = rr2 + 1e-12f;
            float rr1 = tpl * __frsqrt_rn(tpl);
            __syncwarp();   // prior iter's stage-3 HE reads done
            uint4 v0 = make_uint4(pk_bf2(fr0, fr1), pk_bf2(fr2, rr1),
                                  pk_bf2(rr2, 0.0f), 0u);
            *reinterpret_cast<uint4*>(&F[lane * SH])     = v0;
            *reinterpret_cast<uint4*>(&F[lane * SH + 4]) = make_uint4(0u, 0u, 0u, 0u);
            __syncwarp();
        }

        // stage 1: T = silu(F @ We1^T + be1)
        {
            uint32_t wv[4]; float2 bb[4];
            #pragma unroll
            for (int nt = 0; nt < 4; nt++) {
                wv[nt] = sFe1[nt * 32 + lane];
                bb[nt] = *reinterpret_cast<const float2*>(&sbe1[8 * nt + 2 * tig]);
            }
            #pragma unroll
            for (int mt = 0; mt < 2; mt++) {
                uint32_t A0 = __float_as_uint(F[(16 * mt + gid) * SH + tig]);
                uint32_t A1 = __float_as_uint(F[(16 * mt + gid + 8) * SH + tig]);
                #pragma unroll
                for (int nt = 0; nt < 4; nt++) {
                    float d0 = bb[nt].x, d1 = bb[nt].y, d2 = bb[nt].x, d3 = bb[nt].y;
                    mma_bf16(d0, d1, d2, d3, A0, A1, 0u, 0u, wv[nt], 0u);
                    int r0 = (16 * mt + gid) * SH + 4 * nt + tig;
                    *reinterpret_cast<uint32_t*>(&Tb[r0]) =
                        pk_bf2(silu_f(d0), silu_f(d1));
                    *reinterpret_cast<uint32_t*>(&Tb[r0 + 8 * SH]) =
                        pk_bf2(silu_f(d2), silu_f(d3));
                }
            }
        }
        __syncwarp();

        // stage 2: HE = T @ We2^T + be2 ; masked he (j>i) -> ps in regs
        {
            uint2 wv[8]; float2 bb[4];
            #pragma unroll
            for (int nt = 0; nt < 4; nt++)
                bb[nt] = *reinterpret_cast<const float2*>(&sbe2[8 * nt + 2 * tig]);
            #pragma unroll
            for (int p = 0; p < 8; p++) wv[p] = sFe2[p * 32 + lane];
            #pragma unroll
            for (int mt = 0; mt < 2; mt++) {
                uint32_t Ar[8];
                #pragma unroll
                for (int kt = 0; kt < 2; kt++) {
                    int base = (16 * mt + gid) * SH + 8 * kt + tig;
                    Ar[4 * kt + 0] = __float_as_uint(Tb[base]);
                    Ar[4 * kt + 1] = __float_as_uint(Tb[base + 8 * SH]);
                    Ar[4 * kt + 2] = __float_as_uint(Tb[base + 4]);
                    Ar[4 * kt + 3] = __float_as_uint(Tb[base + 8 * SH + 4]);
                }
                const int j0 = 16 * mt + gid, j1 = j0 + 8;
                const bool plo = (j0 > i), phi = (j1 > i);
                #pragma unroll
                for (int nt = 0; nt < 4; nt++) {
                    float d0 = bb[nt].x, d1 = bb[nt].y, d2 = bb[nt].x, d3 = bb[nt].y;
                    #pragma unroll
                    for (int kt = 0; kt < 2; kt++)
                        mma_bf16(d0, d1, d2, d3,
                                 Ar[4 * kt], Ar[4 * kt + 1], Ar[4 * kt + 2], Ar[4 * kt + 3],
                                 wv[nt * 2 + kt].x, wv[nt * 2 + kt].y);
                    int r0 = (16 * mt + gid) * SH + 4 * nt + tig;
                    *reinterpret_cast<uint32_t*>(&HE[r0])          = pk_bf2(d0, d1);
                    *reinterpret_cast<uint32_t*>(&HE[r0 + 8 * SH]) = pk_bf2(d2, d3);
                    if (plo) { ps[nt * 2] += d0; ps[nt * 2 + 1] += d1; }
                    if (phi) { ps[nt * 2] += d2; ps[nt * 2 + 1] += d3; }
                }
            }
        }
        __syncwarp();

        // stage 3: T = silu(HE @ Wu1a^T + q_i[col] + s_j[row][col])
        {
            uint2 wv[8]; float2 qv[4];
            #pragma unroll
            for (int nt = 0; nt < 4; nt++)
                qv[nt] = *reinterpret_cast<const float2*>(&sq[i * SN + 8 * nt + 2 * tig]);
            #pragma unroll
            for (int p = 0; p < 8; p++) wv[p] = sFu1[p * 32 + lane];
            #pragma unroll
            for (int mt = 0; mt < 2; mt++) {
                uint32_t Ar[8];
                #pragma unroll
                for (int kt = 0; kt < 2; kt++) {
                    int base = (16 * mt + gid) * SH + 8 * kt + tig;
                    Ar[4 * kt + 0] = __float_as_uint(HE[base]);
                    Ar[4 * kt + 1] = __float_as_uint(HE[base + 8 * SH]);
                    Ar[4 * kt + 2] = __float_as_uint(HE[base + 4]);
                    Ar[4 * kt + 3] = __float_as_uint(HE[base + 8 * SH + 4]);
                }
                #pragma unroll
                for (int nt = 0; nt < 4; nt++) {
                    int col = 8 * nt + 2 * tig;
                    float2 s0 = *reinterpret_cast<const float2*>(&ssj[(16 * mt + gid) * SN + col]);
                    float2 s1 = *reinterpret_cast<const float2*>(&ssj[(16 * mt + gid + 8) * SN + col]);
                    float d0 = qv[nt].x + s0.x, d1 = qv[nt].y + s0.y;
                    float d2 = qv[nt].x + s1.x, d3 = qv[nt].y + s1.y;
                    #pragma unroll
                    for (int kt = 0; kt < 2; kt++)
                        mma_bf16(d0, d1, d2, d3,
                                 Ar[4 * kt], Ar[4 * kt + 1], Ar[4 * kt + 2], Ar[4 * kt + 3],
                                 wv[nt * 2 + kt].x, wv[nt * 2 + kt].y);
                    int r0 = (16 * mt + gid) * SH + 4 * nt + tig;
                    *reinterpret_cast<uint32_t*>(&Tb[r0]) =
                        pk_bf2(silu_f(d0), silu_f(d1));
                    *reinterpret_cast<uint32_t*>(&Tb[r0 + 8 * SH]) =
                        pk_bf2(silu_f(d2), silu_f(d3));
                }
            }
        }
        __syncwarp();

        // stage 4: hn = T @ Wu2^T + bu2 -- NO stores; masked adds into rs/ps
        {
            uint2 wv[8]; float2 bb[4];
            float rs[8];
            #pragma unroll
            for (int v = 0; v < 8; v++) rs[v] = 0.0f;
            #pragma unroll
            for (int nt = 0; nt < 4; nt++)
                bb[nt] = *reinterpret_cast<const float2*>(&sbu2[8 * nt + 2 * tig]);
            #pragma unroll
            for (int p = 0; p < 8; p++) wv[p] = sFu2[p * 32 + lane];
            #pragma unroll
            for (int mt = 0; mt < 2; mt++) {
                uint32_t Ar[8];
                #pragma unroll
                for (int kt = 0; kt < 2; kt++) {
                    int base = (16 * mt + gid) * SH + 8 * kt + tig;
                    Ar[4 * kt + 0] = __float_as_uint(Tb[base]);
                    Ar[4 * kt + 1] = __float_as_uint(Tb[base + 8 * SH]);
                    Ar[4 * kt + 2] = __float_as_uint(Tb[base + 4]);
                    Ar[4 * kt + 3] = __float_as_uint(Tb[base + 8 * SH + 4]);
                }
                const int j0 = 16 * mt + gid, j1 = j0 + 8;
                const bool plo = (j0 > i),  phi = (j1 > i);
                const bool nlo = (j0 != i), nhi = (j1 != i);
                #pragma unroll
                for (int nt = 0; nt < 4; nt++) {
                    float d0 = bb[nt].x, d1 = bb[nt].y, d2 = bb[nt].x, d3 = bb[nt].y;
                    #pragma unroll
                    for (int kt = 0; kt < 2; kt++)
                        mma_bf16(d0, d1, d2, d3,
                                 Ar[4 * kt], Ar[4 * kt + 1], Ar[4 * kt + 2], Ar[4 * kt + 3],
                                 wv[nt * 2 + kt].x, wv[nt * 2 + kt].y);
                    if (nlo) { rs[nt * 2] += d0; rs[nt * 2 + 1] += d1; }
                    if (nhi) { rs[nt * 2] += d2; rs[nt * 2 + 1] += d3; }
                    if (plo) { ps[nt * 2] += d0; ps[nt * 2 + 1] += d1; }
                    if (phi) { ps[nt * 2] += d2; ps[nt * 2 + 1] += d3; }
                }
            }
            #pragma unroll
            for (int v = 0; v < 8; v++) {
                rs[v] += __shfl_xor_sync(0xffffffffu, rs[v], 4);
                rs[v] += __shfl_xor_sync(0xffffffffu, rs[v], 8);
                rs[v] += __shfl_xor_sync(0xffffffffu, rs[v], 16);
            }
            if (gid == 0) {
                #pragma unroll
                for (int nt = 0; nt < 4; nt++) {
                    srs[i * SN + 8 * nt + 2 * tig]     = rs[nt * 2];
                    srs[i * SN + 8 * nt + 2 * tig + 1] = rs[nt * 2 + 1];
                }
            }
        }
    }

    // pair-sum: butterfly then one atomic set per warp
    #pragma unroll
    for (int v = 0; v < 8; v++) {
        ps[v] += __shfl_xor_sync(0xffffffffu, ps[v], 4);
        ps[v] += __shfl_xor_sync(0xffffffffu, ps[v], 8);
        ps[v] += __shfl_xor_sync(0xffffffffu, ps[v], 16);
    }
    if (gid == 0) {
        #pragma unroll
        for (int nt = 0; nt < 4; nt++) {
            atomicAdd(&spair[8 * nt + 2 * tig],     ps[nt * 2]);
            atomicAdd(&spair[8 * nt + 2 * tig + 1], ps[nt * 2 + 1]);
        }
    }
    __syncthreads();

    // ---- m_v = We2v @ rowsum  (reuse sp) ----
    {
        int i = lane;
        float4 acc = make_float4(0.f, 0.f, 0.f, 0.f);
        #pragma unroll
        for (int hq = 0; hq < 8; hq++) {
            float4 rv = *reinterpret_cast<const float4*>(&srs[i * SN + 4 * hq]);
            acc.x = fmaf(1.0f, dot4(*reinterpret_cast<const float4*>(&We2v[(ch0 + 0) * 32 + 4 * hq]), rv), acc.x);
            acc.y = fmaf(1.0f, dot4(*reinterpret_cast<const float4*>(&We2v[(ch0 + 1) * 32 + 4 * hq]), rv), acc.y);
            acc.z = fmaf(1.0f, dot4(*reinterpret_cast<const float4*>(&We2v[(ch0 + 2) * 32 + 4 * hq]), rv), acc.z);
            acc.w = fmaf(1.0f, dot4(*reinterpret_cast<const float4*>(&We2v[(ch0 + 3) * 32 + 4 * hq]), rv), acc.w);
        }
        *reinterpret_cast<float4*>(&sp[i * SN + ch0]) = acc;
    }
    __syncthreads();

    // ---- a1 = silu(Wn1 @ [h_v, m_v] + bn1)  (reuse sq) ----
    {
        int i = lane;
        float4 acc = make_float4(bn1[ch0], bn1[ch0 + 1], bn1[ch0 + 2], bn1[ch0 + 3]);
        #pragma unroll
        for (int hq = 0; hq < 8; hq++) {
            float4 av = *reinterpret_cast<const float4*>(&shv[i * SN + 4 * hq]);
            acc.x = fmaf(1.0f, dot4(*reinterpret_cast<const float4*>(&Wn1[(ch0 + 0) * 64 + 4 * hq]), av), acc.x);
            acc.y = fmaf(1.0f, dot4(*reinterpret_cast<const float4*>(&Wn1[(ch0 + 1) * 64 + 4 * hq]), av), acc.y);
            acc.z = fmaf(1.0f, dot4(*reinterpret_cast<const float4*>(&Wn1[(ch0 + 2) * 64 + 4 * hq]), av), acc.z);
            acc.w = fmaf(1.0f, dot4(*reinterpret_cast<const float4*>(&Wn1[(ch0 + 3) * 64 + 4 * hq]), av), acc.w);
        }
        #pragma unroll
        for (int hq = 0; hq < 8; hq++) {
            float4 mv = *reinterpret_cast<const float4*>(&sp[i * SN + 4 * hq]);
            acc.x = fmaf(1.0f, dot4(*reinterpret_cast<const float4*>(&Wn1[(ch0 + 0) * 64 + 32 + 4 * hq]), mv), acc.x);
            acc.y = fmaf(1.0f, dot4(*reinterpret_cast<const float4*>(&Wn1[(ch0 + 1) * 64 + 32 + 4 * hq]), mv), acc.y);
            acc.z = fmaf(1.0f, dot4(*reinterpret_cast<const float4*>(&Wn1[(ch0 + 2) * 64 + 32 + 4 * hq]), mv), acc.z);
            acc.w = fmaf(1.0f, dot4(*reinterpret_cast<const float4*>(&Wn1[(ch0 + 3) * 64 + 32 + 4 * hq]), mv), acc.w);
        }
        acc.x = silu_f(acc.x); acc.y = silu_f(acc.y);
        acc.z = silu_f(acc.z); acc.w = silu_f(acc.w);
        __syncthreads();
        *reinterpret_cast<float4*>(&sq[i * SN + ch0]) = acc;
    }
    __syncthreads();

    // ---- h_v_new = h_v + Wn2 @ a1 + bn2  (reuse ssj) ----
    {
        int i = lane;
        float4 acc;
        float4 hv = *reinterpret_cast<const float4*>(&shv[i * SN + ch0]);
        acc.x = hv.x + bn2[ch0 + 0];
        acc.y = hv.y + bn2[ch0 + 1];
        acc.z = hv.z + bn2[ch0 + 2];
        acc.w = hv.w + bn2[ch0 + 3];
        #pragma unroll
        for (int hq = 0; hq < 8; hq++) {
            float4 av = *reinterpret_cast<const float4*>(&sq[i * SN + 4 * hq]);
            acc.x = fmaf(1.0f, dot4(*reinterpret_cast<const float4*>(&Wn2[(ch0 + 0) * 32 + 4 * hq]), av), acc.x);
            acc.y = fmaf(1.0f, dot4(*reinterpret_cast<const float4*>(&Wn2[(ch0 + 1) * 32 + 4 * hq]), av), acc.y);
            acc.z = fmaf(1.0f, dot4(*reinterpret_cast<const float4*>(&Wn2[(ch0 + 2) * 32 + 4 * hq]), av), acc.z);
            acc.w = fmaf(1.0f, dot4(*reinterpret_cast<const float4*>(&Wn2[(ch0 + 3) * 32 + 4 * hq]), av), acc.w);
        }
        *reinterpret_cast<float4*>(&ssj[i * SN + ch0]) = acc;
    }

    // ---- pairwise scalars ----
    float r2_l = 0.0f, s1_l = 0.0f, cusp_l = 0.0f;
    if (tid < 96) r2_l = sx[tid] * sx[tid];
    for (int idx = tid; idx < 496; idx += 256) {
        int rem = idx, pi = 0, cnt = 31;
        while (rem >= cnt) { rem -= cnt; pi++; cnt--; }
        int pj = pi + 1 + rem;
        float d0 = sx[pi * 3 + 0] - sx[pj * 3 + 0];
        float d1 = sx[pi * 3 + 1] - sx[pj * 3 + 1];
        float d2 = sx[pi * 3 + 2] - sx[pj * 3 + 2];
        float dd = fmaf(d0, d0, fmaf(d1, d1, d2 * d2));
        s1_l += log1pf((dd + 1e-8f) * 25.0f);
        float rc = sqrtf(dd + 1e-30f);
        bool same = (pi < 16) == (pj < 16);
        float gamma = same ? 0.25f : 0.5f;
        cusp_l += gamma * rc * __expf(-rc);
    }
    #pragma unroll
    for (int s = 16; s > 0; s >>= 1) {
        r2_l   += __shfl_xor_sync(0xffffffffu, r2_l,   s);
        s1_l   += __shfl_xor_sync(0xffffffffu, s1_l,   s);
        cusp_l += __shfl_xor_sync(0xffffffffu, cusp_l, s);
    }
    if (lane == 0) {
        atomicAdd(&sred[0], r2_l);
        atomicAdd(&sred[1], s1_l);
        atomicAdd(&sred[2], cusp_l);
    }
    __syncthreads();

    // ---- assemble f_in (130) ----
    if (tid < 32) {
        float hs = 0.0f;
        #pragma unroll
        for (int i2 = 0; i2 < 32; i2++) hs += ssj[i2 * SN + tid];
        sfin[tid]      = hs;
        sfin[32 + tid] = hs * (1.0f / 32.0f);
        float p2 = spair[tid];
        sfin[64 + tid] = p2;
        sfin[96 + tid] = p2 * (1.0f / 496.0f);
    }
    if (tid == 0) {
        sfin[128] = sred[0] * (1.0f / 96.0f);
        sfin[129] = sred[1] * (1.0f / 496.0f);
        sfin[130] = 0.0f;  sfin[131] = 0.0f;
    }
    __syncthreads();

    // ---- readout: 130 -> 64 -> 64 -> 1 ----
    #pragma unroll 1
    for (int oo = 0; oo < 8; oo++) {
        int o = w * 8 + oo;
        float a = 0.0f;
        a = fmaf(Wf1[o * 130 + lane],      sfin[lane],      a);
        a = fmaf(Wf1[o * 130 + lane + 32], sfin[lane + 32], a);
        a = fmaf(Wf1[o * 130 + lane + 64], sfin[lane + 64], a);
        a = fmaf(Wf1[o * 130 + lane + 96], sfin[lane + 96], a);
        if (lane < 2) a = fmaf(Wf1[o * 130 + lane + 128], sfin[lane + 128], a);
        #pragma unroll
        for (int s = 16; s > 0; s >>= 1) a += __shfl_xor_sync(0xffffffffu, a, s);
        if (lane == 0) sf1[o] = silu_f(a + bf1[o]);
    }
    __syncthreads();

    #pragma unroll 1
    for (int oo = 0; oo < 8; oo++) {
        int o = w * 8 + oo;
        float a = fmaf(Wf2[o * 64 + lane],      sf1[lane],      0.0f);
        a       = fmaf(Wf2[o * 64 + lane + 32], sf1[lane + 32], a);
        #pragma unroll
        for (int s = 16; s > 0; s >>= 1) a += __shfl_xor_sync(0xffffffffu, a, s);
        if (lane == 0) sf2[o] = silu_f(a + bf2[o]);
    }
    __syncthreads();

    if (w == 0) {
        float a = fmaf(Wf3[lane],      sf2[lane],      0.0f);
        a       = fmaf(Wf3[lane + 32], sf2[lane + 32], a);
        #pragma unroll
        for (int s = 16; s > 0; s >>= 1) a += __shfl_xor_sync(0xffffffffu, a, s);
        if (lane == 0) out[b] = a + bf3[0] + sred[2];
    }
}

extern "C" void kernel_launch(void* const* d_in, const int* in_sizes, int n_in,
                              void* d_out, int out_size)
{
    const float* x      = (const float*)d_in[0];
    const float* W_node = (const float*)d_in[1];
    const float* b_node = (const float*)d_in[2];
    const float* We1    = (const float*)d_in[3];
    const float* be1    = (const float*)d_in[4];
    const float* We2    = (const float*)d_in[5];
    const float* be2    = (const float*)d_in[6];
    const float* Wv2e   = (const float*)d_in[7];
    const float* We2v   = (const float*)d_in[8];
    const float* Wu1    = (const float*)d_in[9];
    const float* bu1    = (const float*)d_in[10];
    const float* Wu2    = (const float*)d_in[11];
    const float* bu2    = (const float*)d_in[12];
    const float* Wn1    = (const float*)d_in[13];
    const float* bn1    = (const float*)d_in[14];
    const float* Wn2    = (const float*)d_in[15];
    const float* bn2    = (const float*)d_in[16];
    const float* Wf1    = (const float*)d_in[17];
    const float* bf1    = (const float*)d_in[18];
    const float* Wf2    = (const float*)d_in[19];
    const float* bf2    = (const float*)d_in[20];
    const float* Wf3    = (const float*)d_in[21];
    const float* bf3    = (const float*)d_in[22];

    const int dyn_smem = 8 * 2 * 32 * SH * (int)sizeof(float);   // 40960 B
    static bool attr_set = false;
    if (!attr_set) {
        cudaFuncSetAttribute(jastrow_kernel,
                             cudaFuncAttributeMaxDynamicSharedMemorySize, dyn_smem);
        attr_set = true;
    }

    int B = in_sizes[0] / 96;   // (B, 32, 3)
    jastrow_kernel<<<B, 256, dyn_smem>>>(x, W_node, b_node, We1, be1, We2, be2,
                                         Wv2e, We2v, Wu1, bu1, Wu2, bu2,
                                         Wn1, bn1, Wn2, bn2,
                                         Wf1, bf1, Wf2, bf2, Wf3, bf3,
                                         (float*)d_out);
}

// round 16
// speedup vs baseline: 2.0307x; 1.0395x over previous
#include <cuda_runtime.h>
#include <cuda_bf16.h>
#include <cstdint>

// CTNNBackflowStyleJastrow: B=1024, N=32, D=3, H=M=32, RH=64
// Persistent grid (296 CTAs, 2/SM); each CTA loops over batch elements,
// amortizing weight fragment-table staging. Edge loop: bf16 m16n8k16 mma,
// in-register masked reductions. Node phases 4-wide vectorized.
// silu via tanh.approx (1 MUFU).

__device__ __forceinline__ float silu_f(float x) {
    float h = 0.5f * x;
    float t;
    asm("tanh.approx.f32 %0, %1;" : "=f"(t) : "f"(h));
    return fmaf(h, t, h);
}
__device__ __forceinline__ uint32_t pk_bf2(float lo, float hi) {
    uint32_t r;
    asm("cvt.rn.bf16x2.f32 %0, %1, %2;" : "=r"(r) : "f"(hi), "f"(lo));
    return r;
}
__device__ __forceinline__ void mma_bf16(float& d0, float& d1, float& d2, float& d3,
                                         uint32_t a0, uint32_t a1, uint32_t a2, uint32_t a3,
                                         uint32_t b0, uint32_t b1) {
    asm volatile("mma.sync.aligned.m16n8k16.row.col.f32.bf16.bf16.f32 "
                 "{%0,%1,%2,%3}, {%4,%5,%6,%7}, {%8,%9}, {%0,%1,%2,%3};"
                 : "+f"(d0), "+f"(d1), "+f"(d2), "+f"(d3)
                 : "r"(a0), "r"(a1), "r"(a2), "r"(a3), "r"(b0), "r"(b1));
}
__device__ __forceinline__ float dot4(float4 a, float4 b) {
    return fmaf(a.x, b.x, fmaf(a.y, b.y, fmaf(a.z, b.z, a.w * b.w)));
}

#define SH 20   // edge buffer row stride (words)
#define SN 36   // node array row stride (words)

__global__ __launch_bounds__(256, 2)
void jastrow_kernel(int B,
                    const float* __restrict__ x,
                    const float* __restrict__ W_node, const float* __restrict__ b_node,
                    const float* __restrict__ We1,  const float* __restrict__ be1,
                    const float* __restrict__ We2,  const float* __restrict__ be2,
                    const float* __restrict__ Wv2e, const float* __restrict__ We2v,
                    const float* __restrict__ Wu1,  const float* __restrict__ bu1,
                    const float* __restrict__ Wu2,  const float* __restrict__ bu2,
                    const float* __restrict__ Wn1,  const float* __restrict__ bn1,
                    const float* __restrict__ Wn2,  const float* __restrict__ bn2,
                    const float* __restrict__ Wf1,  const float* __restrict__ bf1,
                    const float* __restrict__ Wf2,  const float* __restrict__ bf2,
                    const float* __restrict__ Wf3,  const float* __restrict__ bf3,
                    float* __restrict__ out)
{
    __shared__ float sx[96];
    __shared__ __align__(16) float shv[32 * SN];
    __shared__ __align__(16) float sp [32 * SN];
    __shared__ __align__(16) float sq [32 * SN];
    __shared__ __align__(16) float ssj[32 * SN];
    __shared__ __align__(16) float srs[32 * SN];
    __shared__ __align__(8) float sbe1[32], sbe2[32], sbu2[32];
    __shared__ float spair[32];
    __shared__ float sred[3];
    __shared__ float sfin[132], sf1[64], sf2[64];
    __shared__ uint32_t sFe1[4 * 32];
    __shared__ __align__(8) uint2 sFe2[8 * 32];
    __shared__ __align__(8) uint2 sFu1[8 * 32];
    __shared__ __align__(8) uint2 sFu2[8 * 32];
    extern __shared__ __align__(16) float dynsmem[];   // per warp: Tb[32*SH] + HE[32*SH]

    const int tid  = threadIdx.x;
    const int lane = tid & 31;
    const int w    = tid >> 5;
    const int gid  = lane >> 2;
    const int tig  = lane & 3;
    const int ch0  = 4 * w;

    // ---- one-time staging: biases + weight fragment tables ----
    if (tid < 32) {
        sbe1[tid] = be1[tid]; sbe2[tid] = be2[tid]; sbu2[tid] = bu2[tid];
    }
    for (int idx = tid; idx < 4 * 32; idx += 256) {
        int nt = idx >> 5, ln = idx & 31;
        int g = ln >> 2, t = ln & 3;
        int n = 8 * nt + g;
        float w0 = (2 * t     < 5) ? We1[n * 5 + 2 * t]     : 0.0f;
        float w1 = (2 * t + 1 < 5) ? We1[n * 5 + 2 * t + 1] : 0.0f;
        sFe1[idx] = pk_bf2(w0, w1);
    }
    for (int idx = tid; idx < 8 * 32; idx += 256) {
        int pair = idx >> 5, ln = idx & 31;
        int nt = pair >> 1, kt = pair & 1;
        int g = ln >> 2, t = ln & 3;
        int n = 8 * nt + g;
        int k = 16 * kt + 2 * t;
        sFe2[idx] = make_uint2(pk_bf2(We2[n * 32 + k],     We2[n * 32 + k + 1]),
                               pk_bf2(We2[n * 32 + k + 8], We2[n * 32 + k + 9]));
        sFu1[idx] = make_uint2(pk_bf2(Wu1[n * 96 + k],     Wu1[n * 96 + k + 1]),
                               pk_bf2(Wu1[n * 96 + k + 8], Wu1[n * 96 + k + 9]));
        sFu2[idx] = make_uint2(pk_bf2(Wu2[n * 32 + k],     Wu2[n * 32 + k + 1]),
                               pk_bf2(Wu2[n * 32 + k + 8], Wu2[n * 32 + k + 9]));
    }

    float* Tb = dynsmem + w * (2 * 32 * SH);
    float* HE = Tb + 32 * SH;
    float* F  = HE;                    // stage-1 feature scratch aliases HE

    // ==== persistent batch loop ====
    for (int b = blockIdx.x; b < B; b += gridDim.x) {

    __syncthreads();                   // prior batch's readers done
    if (tid < 96) sx[tid] = x[b * 96 + tid];
    if (tid < 32) spair[tid] = 0.0f;
    if (tid < 3)  sred[tid] = 0.0f;
    __syncthreads();

    // ---- h_v ----
    {
        int i = lane;
        float sf = (i >= 16) ? 1.0f : 0.0f;
        float4 xin = make_float4(sx[i * 3 + 0], sx[i * 3 + 1], sx[i * 3 + 2], sf);
        float4 acc;
        acc.x = b_node[ch0 + 0] + dot4(*reinterpret_cast<const float4*>(&W_node[(ch0 + 0) * 4]), xin);
        acc.y = b_node[ch0 + 1] + dot4(*reinterpret_cast<const float4*>(&W_node[(ch0 + 1) * 4]), xin);
        acc.z = b_node[ch0 + 2] + dot4(*reinterpret_cast<const float4*>(&W_node[(ch0 + 2) * 4]), xin);
        acc.w = b_node[ch0 + 3] + dot4(*reinterpret_cast<const float4*>(&W_node[(ch0 + 3) * 4]), xin);
        *reinterpret_cast<float4*>(&shv[i * SN + ch0]) = acc;
    }
    __syncthreads();

    // ---- p = h_v @ Wv2e^T ----
    {
        int i = lane;
        float4 acc = make_float4(0.f, 0.f, 0.f, 0.f);
        #pragma unroll
        for (int hq = 0; hq < 8; hq++) {
            float4 av = *reinterpret_cast<const float4*>(&shv[i * SN + 4 * hq]);
            acc.x += dot4(*reinterpret_cast<const float4*>(&Wv2e[(ch0 + 0) * 32 + 4 * hq]), av);
            acc.y += dot4(*reinterpret_cast<const float4*>(&Wv2e[(ch0 + 1) * 32 + 4 * hq]), av);
            acc.z += dot4(*reinterpret_cast<const float4*>(&Wv2e[(ch0 + 2) * 32 + 4 * hq]), av);
            acc.w += dot4(*reinterpret_cast<const float4*>(&Wv2e[(ch0 + 3) * 32 + 4 * hq]), av);
        }
        *reinterpret_cast<float4*>(&sp[i * SN + ch0]) = acc;
    }
    __syncthreads();

    // ---- q_i, s_j ----
    {
        int i = lane;
        float4 aq = make_float4(bu1[ch0], bu1[ch0 + 1], bu1[ch0 + 2], bu1[ch0 + 3]);
        float4 as = make_float4(0.f, 0.f, 0.f, 0.f);
        #pragma unroll
        for (int hq = 0; hq < 8; hq++) {
            float4 pv = *reinterpret_cast<const float4*>(&sp[i * SN + 4 * hq]);
            aq.x += dot4(*reinterpret_cast<const float4*>(&Wu1[(ch0 + 0) * 96 + 32 + 4 * hq]), pv);
            aq.y += dot4(*reinterpret_cast<const float4*>(&Wu1[(ch0 + 1) * 96 + 32 + 4 * hq]), pv);
            aq.z += dot4(*reinterpret_cast<const float4*>(&Wu1[(ch0 + 2) * 96 + 32 + 4 * hq]), pv);
            aq.w += dot4(*reinterpret_cast<const float4*>(&Wu1[(ch0 + 3) * 96 + 32 + 4 * hq]), pv);
            as.x += dot4(*reinterpret_cast<const float4*>(&Wu1[(ch0 + 0) * 96 + 64 + 4 * hq]), pv);
            as.y += dot4(*reinterpret_cast<const float4*>(&Wu1[(ch0 + 1) * 96 + 64 + 4 * hq]), pv);
            as.z += dot4(*reinterpret_cast<const float4*>(&Wu1[(ch0 + 2) * 96 + 64 + 4 * hq]), pv);
            as.w += dot4(*reinterpret_cast<const float4*>(&Wu1[(ch0 + 3) * 96 + 64 + 4 * hq]), pv);
        }
        *reinterpret_cast<float4*>(&sq [i * SN + ch0]) = aq;
        *reinterpret_cast<float4*>(&ssj[i * SN + ch0]) = as;
    }
    __syncthreads();

    // ---- edge loop: warp w owns rows i = 4w..4w+3 ----
    const float xj0 = sx[lane * 3 + 0], xj1 = sx[lane * 3 + 1], xj2 = sx[lane * 3 + 2];
    float ps[8];
    #pragma unroll
    for (int v = 0; v < 8; v++) ps[v] = 0.0f;

    #pragma unroll 1
    for (int ii = 0; ii < 4; ii++) {
        const int i = w * 4 + ii;

        // features (lane = edge j)
        {
            float fr0 = sx[i * 3 + 0] - xj0;
            float fr1 = sx[i * 3 + 1] - xj1;
            float fr2 = sx[i * 3 + 2] - xj2;
            float rr2 = fmaf(fr0, fr0, fmaf(fr1, fr1, fr2 * fr2));
            float tpl = rr2 + 1e-12f;
            float rr1 = tpl * __frsqrt_rn(tpl);
            __syncwarp();   // prior iter's stage-3 HE reads done
            uint4 v0 = make_uint4(pk_bf2(fr0, fr1), pk_bf2(fr2, rr1),
                                  pk_bf2(rr2, 0.0f), 0u);
            *reinterpret_cast<uint4*>(&F[lane * SH])     = v0;
            *reinterpret_cast<uint4*>(&F[lane * SH + 4]) = make_uint4(0u, 0u, 0u, 0u);
            __syncwarp();
        }

        // stage 1: T = silu(F @ We1^T + be1)
        {
            uint32_t wv[4]; float2 bb[4];
            #pragma unroll
            for (int nt = 0; nt < 4; nt++) {
                wv[nt] = sFe1[nt * 32 + lane];
                bb[nt] = *reinterpret_cast<const float2*>(&sbe1[8 * nt + 2 * tig]);
            }
            #pragma unroll
            for (int mt = 0; mt < 2; mt++) {
                uint32_t A0 = __float_as_uint(F[(16 * mt + gid) * SH + tig]);
                uint32_t A1 = __float_as_uint(F[(16 * mt + gid + 8) * SH + tig]);
                #pragma unroll
                for (int nt = 0; nt < 4; nt++) {
                    float d0 = bb[nt].x, d1 = bb[nt].y, d2 = bb[nt].x, d3 = bb[nt].y;
                    mma_bf16(d0, d1, d2, d3, A0, A1, 0u, 0u, wv[nt], 0u);
                    int r0 = (16 * mt + gid) * SH + 4 * nt + tig;
                    *reinterpret_cast<uint32_t*>(&Tb[r0]) =
                        pk_bf2(silu_f(d0), silu_f(d1));
                    *reinterpret_cast<uint32_t*>(&Tb[r0 + 8 * SH]) =
                        pk_bf2(silu_f(d2), silu_f(d3));
                }
            }
        }
        __syncwarp();

        // stage 2: HE = T @ We2^T + be2 ; masked he (j>i) -> ps in regs
        {
            uint2 wv[8]; float2 bb[4];
            #pragma unroll
            for (int nt = 0; nt < 4; nt++)
                bb[nt] = *reinterpret_cast<const float2*>(&sbe2[8 * nt + 2 * tig]);
            #pragma unroll
            for (int p = 0; p < 8; p++) wv[p] = sFe2[p * 32 + lane];
            #pragma unroll
            for (int mt = 0; mt < 2; mt++) {
                uint32_t Ar[8];
                #pragma unroll
                for (int kt = 0; kt < 2; kt++) {
                    int base = (16 * mt + gid) * SH + 8 * kt + tig;
                    Ar[4 * kt + 0] = __float_as_uint(Tb[base]);
                    Ar[4 * kt + 1] = __float_as_uint(Tb[base + 8 * SH]);
                    Ar[4 * kt + 2] = __float_as_uint(Tb[base + 4]);
                    Ar[4 * kt + 3] = __float_as_uint(Tb[base + 8 * SH + 4]);
                }
                const int j0 = 16 * mt + gid, j1 = j0 + 8;
                const bool plo = (j0 > i), phi = (j1 > i);
                #pragma unroll
                for (int nt = 0; nt < 4; nt++) {
                    float d0 = bb[nt].x, d1 = bb[nt].y, d2 = bb[nt].x, d3 = bb[nt].y;
                    #pragma unroll
                    for (int kt = 0; kt < 2; kt++)
                        mma_bf16(d0, d1, d2, d3,
                                 Ar[4 * kt], Ar[4 * kt + 1], Ar[4 * kt + 2], Ar[4 * kt + 3],
                                 wv[nt * 2 + kt].x, wv[nt * 2 + kt].y);
                    int r0 = (16 * mt + gid) * SH + 4 * nt + tig;
                    *reinterpret_cast<uint32_t*>(&HE[r0])          = pk_bf2(d0, d1);
                    *reinterpret_cast<uint32_t*>(&HE[r0 + 8 * SH]) = pk_bf2(d2, d3);
                    if (plo) { ps[nt * 2] += d0; ps[nt * 2 + 1] += d1; }
                    if (phi) { ps[nt * 2] += d2; ps[nt * 2 + 1] += d3; }
                }
            }
        }
        __syncwarp();

        // stage 3: T = silu(HE @ Wu1a^T + q_i[col] + s_j[row][col])
        {
            uint2 wv[8]; float2 qv[4];
            #pragma unroll
            for (int nt = 0; nt < 4; nt++)
                qv[nt] = *reinterpret_cast<const float2*>(&sq[i * SN + 8 * nt + 2 * tig]);
            #pragma unroll
            for (int p = 0; p < 8; p++) wv[p] = sFu1[p * 32 + lane];
            #pragma unroll
            for (int mt = 0; mt < 2; mt++) {
                uint32_t Ar[8];
                #pragma unroll
                for (int kt = 0; kt < 2; kt++) {
                    int base = (16 * mt + gid) * SH + 8 * kt + tig;
                    Ar[4 * kt + 0] = __float_as_uint(HE[base]);
                    Ar[4 * kt + 1] = __float_as_uint(HE[base + 8 * SH]);
                    Ar[4 * kt + 2] = __float_as_uint(HE[base + 4]);
                    Ar[4 * kt + 3] = __float_as_uint(HE[base + 8 * SH + 4]);
                }
                #pragma unroll
                for (int nt = 0; nt < 4; nt++) {
                    int col = 8 * nt + 2 * tig;
                    float2 s0 = *reinterpret_cast<const float2*>(&ssj[(16 * mt + gid) * SN + col]);
                    float2 s1 = *reinterpret_cast<const float2*>(&ssj[(16 * mt + gid + 8) * SN + col]);
                    float d0 = qv[nt].x + s0.x, d1 = qv[nt].y + s0.y;
                    float d2 = qv[nt].x + s1.x, d3 = qv[nt].y + s1.y;
                    #pragma unroll
                    for (int kt = 0; kt < 2; kt++)
                        mma_bf16(d0, d1, d2, d3,
                                 Ar[4 * kt], Ar[4 * kt + 1], Ar[4 * kt + 2], Ar[4 * kt + 3],
                                 wv[nt * 2 + kt].x, wv[nt * 2 + kt].y);
                    int r0 = (16 * mt + gid) * SH + 4 * nt + tig;
                    *reinterpret_cast<uint32_t*>(&Tb[r0]) =
                        pk_bf2(silu_f(d0), silu_f(d1));
                    *reinterpret_cast<uint32_t*>(&Tb[r0 + 8 * SH]) =
                        pk_bf2(silu_f(d2), silu_f(d3));
                }
            }
        }
        __syncwarp();

        // stage 4: hn = T @ Wu2^T + bu2 -- NO stores; masked adds into rs/ps
        {
            uint2 wv[8]; float2 bb[4];
            float rs[8];
            #pragma unroll
            for (int v = 0; v < 8; v++) rs[v] = 0.0f;
            #pragma unroll
            for (int nt = 0; nt < 4; nt++)
                bb[nt] = *reinterpret_cast<const float2*>(&sbu2[8 * nt + 2 * tig]);
            #pragma unroll
            for (int p = 0; p < 8; p++) wv[p] = sFu2[p * 32 + lane];
            #pragma unroll
            for (int mt = 0; mt < 2; mt++) {
                uint32_t Ar[8];
                #pragma unroll
                for (int kt = 0; kt < 2; kt++) {
                    int base = (16 * mt + gid) * SH + 8 * kt + tig;
                    Ar[4 * kt + 0] = __float_as_uint(Tb[base]);
                    Ar[4 * kt + 1] = __float_as_uint(Tb[base + 8 * SH]);
                    Ar[4 * kt + 2] = __float_as_uint(Tb[base + 4]);
                    Ar[4 * kt + 3] = __float_as_uint(Tb[base + 8 * SH + 4]);
                }
                const int j0 = 16 * mt + gid, j1 = j0 + 8;
                const bool plo = (j0 > i),  phi = (j1 > i);
                const bool nlo = (j0 != i), nhi = (j1 != i);
                #pragma unroll
                for (int nt = 0; nt < 4; nt++) {
                    float d0 = bb[nt].x, d1 = bb[nt].y, d2 = bb[nt].x, d3 = bb[nt].y;
                    #pragma unroll
                    for (int kt = 0; kt < 2; kt++)
                        mma_bf16(d0, d1, d2, d3,
                                 Ar[4 * kt], Ar[4 * kt + 1], Ar[4 * kt + 2], Ar[4 * kt + 3],
                                 wv[nt * 2 + kt].x, wv[nt * 2 + kt].y);
                    if (nlo) { rs[nt * 2] += d0; rs[nt * 2 + 1] += d1; }
                    if (nhi) { rs[nt * 2] += d2; rs[nt * 2 + 1] += d3; }
                    if (plo) { ps[nt * 2] += d0; ps[nt * 2 + 1] += d1; }
                    if (phi) { ps[nt * 2] += d2; ps[nt * 2 + 1] += d3; }
                }
            }
            #pragma unroll
            for (int v = 0; v < 8; v++) {
                rs[v] += __shfl_xor_sync(0xffffffffu, rs[v], 4);
                rs[v] += __shfl_xor_sync(0xffffffffu, rs[v], 8);
                rs[v] += __shfl_xor_sync(0xffffffffu, rs[v], 16);
            }
            if (gid == 0) {
                #pragma unroll
                for (int nt = 0; nt < 4; nt++) {
                    srs[i * SN + 8 * nt + 2 * tig]     = rs[nt * 2];
                    srs[i * SN + 8 * nt + 2 * tig + 1] = rs[nt * 2 + 1];
                }
            }
        }
    }

    // pair-sum: butterfly then one atomic set per warp
    #pragma unroll
    for (int v = 0; v < 8; v++) {
        ps[v] += __shfl_xor_sync(0xffffffffu, ps[v], 4);
        ps[v] += __shfl_xor_sync(0xffffffffu, ps[v], 8);
        ps[v] += __shfl_xor_sync(0xffffffffu, ps[v], 16);
    }
    if (gid == 0) {
        #pragma unroll
        for (int nt = 0; nt < 4; nt++) {
            atomicAdd(&spair[8 * nt + 2 * tig],     ps[nt * 2]);
            atomicAdd(&spair[8 * nt + 2 * tig + 1], ps[nt * 2 + 1]);
        }
    }
    __syncthreads();

    // ---- m_v = We2v @ rowsum  (reuse sp) ----
    {
        int i = lane;
        float4 acc = make_float4(0.f, 0.f, 0.f, 0.f);
        #pragma unroll
        for (int hq = 0; hq < 8; hq++) {
            float4 rv = *reinterpret_cast<const float4*>(&srs[i * SN + 4 * hq]);
            acc.x += dot4(*reinterpret_cast<const float4*>(&We2v[(ch0 + 0) * 32 + 4 * hq]), rv);
            acc.y += dot4(*reinterpret_cast<const float4*>(&We2v[(ch0 + 1) * 32 + 4 * hq]), rv);
            acc.z += dot4(*reinterpret_cast<const float4*>(&We2v[(ch0 + 2) * 32 + 4 * hq]), rv);
            acc.w += dot4(*reinterpret_cast<const float4*>(&We2v[(ch0 + 3) * 32 + 4 * hq]), rv);
        }
        *reinterpret_cast<float4*>(&sp[i * SN + ch0]) = acc;
    }
    __syncthreads();

    // ---- a1 = silu(Wn1 @ [h_v, m_v] + bn1)  (reuse sq) ----
    {
        int i = lane;
        float4 acc = make_float4(bn1[ch0], bn1[ch0 + 1], bn1[ch0 + 2], bn1[ch0 + 3]);
        #pragma unroll
        for (int hq = 0; hq < 8; hq++) {
            float4 av = *reinterpret_cast<const float4*>(&shv[i * SN + 4 * hq]);
            acc.x += dot4(*reinterpret_cast<const float4*>(&Wn1[(ch0 + 0) * 64 + 4 * hq]), av);
            acc.y += dot4(*reinterpret_cast<const float4*>(&Wn1[(ch0 + 1) * 64 + 4 * hq]), av);
            acc.z += dot4(*reinterpret_cast<const float4*>(&Wn1[(ch0 + 2) * 64 + 4 * hq]), av);
            acc.w += dot4(*reinterpret_cast<const float4*>(&Wn1[(ch0 + 3) * 64 + 4 * hq]), av);
        }
        #pragma unroll
        for (int hq = 0; hq < 8; hq++) {
            float4 mv = *reinterpret_cast<const float4*>(&sp[i * SN + 4 * hq]);
            acc.x += dot4(*reinterpret_cast<const float4*>(&Wn1[(ch0 + 0) * 64 + 32 + 4 * hq]), mv);
            acc.y += dot4(*reinterpret_cast<const float4*>(&Wn1[(ch0 + 1) * 64 + 32 + 4 * hq]), mv);
            acc.z += dot4(*reinterpret_cast<const float4*>(&Wn1[(ch0 + 2) * 64 + 32 + 4 * hq]), mv);
            acc.w += dot4(*reinterpret_cast<const float4*>(&Wn1[(ch0 + 3) * 64 + 32 + 4 * hq]), mv);
        }
        acc.x = silu_f(acc.x); acc.y = silu_f(acc.y);
        acc.z = silu_f(acc.z); acc.w = silu_f(acc.w);
        __syncthreads();
        *reinterpret_cast<float4*>(&sq[i * SN + ch0]) = acc;
    }
    __syncthreads();

    // ---- h_v_new = h_v + Wn2 @ a1 + bn2  (reuse ssj) ----
    {
        int i = lane;
        float4 acc;
        float4 hv = *reinterpret_cast<const float4*>(&shv[i * SN + ch0]);
        acc.x = hv.x + bn2[ch0 + 0];
        acc.y = hv.y + bn2[ch0 + 1];
        acc.z = hv.z + bn2[ch0 + 2];
        acc.w = hv.w + bn2[ch0 + 3];
        #pragma unroll
        for (int hq = 0; hq < 8; hq++) {
            float4 av = *reinterpret_cast<const float4*>(&sq[i * SN + 4 * hq]);
            acc.x += dot4(*reinterpret_cast<const float4*>(&Wn2[(ch0 + 0) * 32 + 4 * hq]), av);
            acc.y += dot4(*reinterpret_cast<const float4*>(&Wn2[(ch0 + 1) * 32 + 4 * hq]), av);
            acc.z += dot4(*reinterpret_cast<const float4*>(&Wn2[(ch0 + 2) * 32 + 4 * hq]), av);
            acc.w += dot4(*reinterpret_cast<const float4*>(&Wn2[(ch0 + 3) * 32 + 4 * hq]), av);
        }
        *reinterpret_cast<float4*>(&ssj[i * SN + ch0]) = acc;
    }

    // ---- pairwise scalars ----
    float r2_l = 0.0f, s1_l = 0.0f, cusp_l = 0.0f;
    if (tid < 96) r2_l = sx[tid] * sx[tid];
    for (int idx = tid; idx < 496; idx += 256) {
        int rem = idx, pi = 0, cnt = 31;
        while (rem >= cnt) { rem -= cnt; pi++; cnt--; }
        int pj = pi + 1 + rem;
        float d0 = sx[pi * 3 + 0] - sx[pj * 3 + 0];
        float d1 = sx[pi * 3 + 1] - sx[pj * 3 + 1];
        float d2 = sx[pi * 3 + 2] - sx[pj * 3 + 2];
        float dd = fmaf(d0, d0, fmaf(d1, d1, d2 * d2));
        s1_l += log1pf((dd + 1e-8f) * 25.0f);
        float rc = sqrtf(dd + 1e-30f);
        bool same = (pi < 16) == (pj < 16);
        float gamma = same ? 0.25f : 0.5f;
        cusp_l += gamma * rc * __expf(-rc);
    }
    #pragma unroll
    for (int s = 16; s > 0; s >>= 1) {
        r2_l   += __shfl_xor_sync(0xffffffffu, r2_l,   s);
        s1_l   += __shfl_xor_sync(0xffffffffu, s1_l,   s);
        cusp_l += __shfl_xor_sync(0xffffffffu, cusp_l, s);
    }
    if (lane == 0) {
        atomicAdd(&sred[0], r2_l);
        atomicAdd(&sred[1], s1_l);
        atomicAdd(&sred[2], cusp_l);
    }
    __syncthreads();

    // ---- assemble f_in (130) ----
    if (tid < 32) {
        float hs = 0.0f;
        #pragma unroll
        for (int i2 = 0; i2 < 32; i2++) hs += ssj[i2 * SN + tid];
        sfin[tid]      = hs;
        sfin[32 + tid] = hs * (1.0f / 32.0f);
        float p2 = spair[tid];
        sfin[64 + tid] = p2;
        sfin[96 + tid] = p2 * (1.0f / 496.0f);
    }
    if (tid == 0) {
        sfin[128] = sred[0] * (1.0f / 96.0f);
        sfin[129] = sred[1] * (1.0f / 496.0f);
        sfin[130] = 0.0f;  sfin[131] = 0.0f;
    }
    __syncthreads();

    // ---- readout: 130 -> 64 -> 64 -> 1 ----
    #pragma unroll 1
    for (int oo = 0; oo < 8; oo++) {
        int o = w * 8 + oo;
        float a = 0.0f;
        a = fmaf(Wf1[o * 130 + lane],      sfin[lane],      a);
        a = fmaf(Wf1[o * 130 + lane + 32], sfin[lane + 32], a);
        a = fmaf(Wf1[o * 130 + lane + 64], sfin[lane + 64], a);
        a = fmaf(Wf1[o * 130 + lane + 96], sfin[lane + 96], a);
        if (lane < 2) a = fmaf(Wf1[o * 130 + lane + 128], sfin[lane + 128], a);
        #pragma unroll
        for (int s = 16; s > 0; s >>= 1) a += __shfl_xor_sync(0xffffffffu, a, s);
        if (lane == 0) sf1[o] = silu_f(a + bf1[o]);
    }
    __syncthreads();

    #pragma unroll 1
    for (int oo = 0; oo < 8; oo++) {
        int o = w * 8 + oo;
        float a = fmaf(Wf2[o * 64 + lane],      sf1[lane],      0.0f);
        a       = fmaf(Wf2[o * 64 + lane + 32], sf1[lane + 32], a);
        #pragma unroll
        for (int s = 16; s > 0; s >>= 1) a += __shfl_xor_sync(0xffffffffu, a, s);
        if (lane == 0) sf2[o] = silu_f(a + bf2[o]);
    }
    __syncthreads();

    if (w == 0) {
        float a = fmaf(Wf3[lane],      sf2[lane],      0.0f);
        a       = fmaf(Wf3[lane + 32], sf2[lane + 32], a);
        #pragma unroll
        for (int s = 16; s > 0; s >>= 1) a += __shfl_xor_sync(0xffffffffu, a, s);
        if (lane == 0) out[b] = a + bf3[0] + sred[2];
    }

    }  // batch loop
}

extern "C" void kernel_launch(void* const* d_in, const int* in_sizes, int n_in,
                              void* d_out, int out_size)
{
    const float* x      = (const float*)d_in[0];
    const float* W_node = (const float*)d_in[1];
    const float* b_node = (const float*)d_in[2];
    const float* We1    = (const float*)d_in[3];
    const float* be1    = (const float*)d_in[4];
    const float* We2    = (const float*)d_in[5];
    const float* be2    = (const float*)d_in[6];
    const float* Wv2e   = (const float*)d_in[7];
    const float* We2v   = (const float*)d_in[8];
    const float* Wu1    = (const float*)d_in[9];
    const float* bu1    = (const float*)d_in[10];
    const float* Wu2    = (const float*)d_in[11];
    const float* bu2    = (const float*)d_in[12];
    const float* Wn1    = (const float*)d_in[13];
    const float* bn1    = (const float*)d_in[14];
    const float* Wn2    = (const float*)d_in[15];
    const float* bn2    = (const float*)d_in[16];
    const float* Wf1    = (const float*)d_in[17];
    const float* bf1    = (const float*)d_in[18];
    const float* Wf2    = (const float*)d_in[19];
    const float* bf2    = (const float*)d_in[20];
    const float* Wf3    = (const float*)d_in[21];
    const float* bf3    = (const float*)d_in[22];

    const int dyn_smem = 8 * 2 * 32 * SH * (int)sizeof(float);   // 40960 B
    static bool attr_set = false;
    if (!attr_set) {
        cudaFuncSetAttribute(jastrow_kernel,
                             cudaFuncAttributeMaxDynamicSharedMemorySize, dyn_smem);
        attr_set = true;
    }

    int B = in_sizes[0] / 96;   // (B, 32, 3)
    int grid = 296;             // 148 SMs x 2 CTAs/SM (persistent)
    if (grid > B) grid = B;
    jastrow_kernel<<<grid, 256, dyn_smem>>>(B, x, W_node, b_node, We1, be1, We2, be2,
                                            Wv2e, We2v, Wu1, bu1, Wu2, bu2,
                                            Wn1, bn1, Wn2, bn2,
                                            Wf1, bf1, Wf2, bf2, Wf3, bf3,
                                            (float*)d_out);
}